// round 2
// baseline (speedup 1.0000x reference)
#include <cuda_runtime.h>
#include <math.h>

#define B_  2
#define S_  2048
#define D_  2048
#define H_  16
#define DK_ 128
#define M_  (B_*S_)   // 4096

// ---------------- scratch (device globals; no allocs allowed) ----------------
__device__ float g_q[B_*H_*S_*DK_];
__device__ float g_k[B_*H_*S_*DK_];
__device__ float g_v[B_*H_*S_*DK_];
__device__ float g_attn[B_*S_*D_];
__device__ float g_cos[S_*64];
__device__ float g_sin[S_*64];

// ---------------- SGEMM: C[m,n] = sum_k A[m,k]*W[n,k] + bias[n] --------------
// A: [M,K] row-major, W: [N,K] row-major. Tile 128x128x16, 256 threads, 8x8/thread.
// headed=1: write to [B,H,S,DK] layout; headed=0: row-major [M,N].
__global__ __launch_bounds__(256) void sgemm_tn(
    const float* __restrict__ A, const float* __restrict__ W,
    const float* __restrict__ bias, float* __restrict__ C,
    int K, int headed)
{
    __shared__ float As[16][128];
    __shared__ float Bs[16][128];
    const int tid = threadIdx.x;
    const int tr = tid >> 4, tc = tid & 15;
    const int m0 = blockIdx.y << 7, n0 = blockIdx.x << 7;
    const int lrow = tid >> 2;          // 0..63
    const int lk   = (tid & 3) << 2;    // 0,4,8,12

    float acc[8][8];
#pragma unroll
    for (int i = 0; i < 8; i++)
#pragma unroll
        for (int j = 0; j < 8; j++) acc[i][j] = 0.f;

    for (int k0 = 0; k0 < K; k0 += 16) {
#pragma unroll
        for (int i = 0; i < 2; i++) {
            int r = lrow + (i << 6);
            float4 va = *(const float4*)(A + (size_t)(m0 + r) * K + k0 + lk);
            As[lk+0][r] = va.x; As[lk+1][r] = va.y; As[lk+2][r] = va.z; As[lk+3][r] = va.w;
            float4 vb = *(const float4*)(W + (size_t)(n0 + r) * K + k0 + lk);
            Bs[lk+0][r] = vb.x; Bs[lk+1][r] = vb.y; Bs[lk+2][r] = vb.z; Bs[lk+3][r] = vb.w;
        }
        __syncthreads();
#pragma unroll
        for (int kk = 0; kk < 16; kk++) {
            float4 a0 = *(const float4*)&As[kk][tr << 2];
            float4 a1 = *(const float4*)&As[kk][64 + (tr << 2)];
            float4 b0 = *(const float4*)&Bs[kk][tc << 2];
            float4 b1 = *(const float4*)&Bs[kk][64 + (tc << 2)];
            float a[8] = {a0.x,a0.y,a0.z,a0.w,a1.x,a1.y,a1.z,a1.w};
            float b[8] = {b0.x,b0.y,b0.z,b0.w,b1.x,b1.y,b1.z,b1.w};
#pragma unroll
            for (int i = 0; i < 8; i++)
#pragma unroll
                for (int j = 0; j < 8; j++)
                    acc[i][j] = fmaf(a[i], b[j], acc[i][j]);
        }
        __syncthreads();
    }

#pragma unroll
    for (int ii = 0; ii < 2; ii++)
#pragma unroll
        for (int i = 0; i < 4; i++) {
            int m = m0 + (ii << 6) + (tr << 2) + i;
#pragma unroll
            for (int jj = 0; jj < 2; jj++) {
                int n = n0 + (jj << 6) + (tc << 2);
                float4 r;
                r.x = acc[ii*4+i][jj*4+0] + bias[n+0];
                r.y = acc[ii*4+i][jj*4+1] + bias[n+1];
                r.z = acc[ii*4+i][jj*4+2] + bias[n+2];
                r.w = acc[ii*4+i][jj*4+3] + bias[n+3];
                if (headed) {
                    int b  = m >> 11;      // m / S_
                    int s  = m & (S_-1);
                    int h  = n >> 7;       // n / DK_
                    int dk = n & (DK_-1);
                    *(float4*)(C + (((size_t)(b*H_ + h) * S_ + s) << 7) + dk) = r;
                } else {
                    *(float4*)(C + (size_t)m * D_ + n) = r;
                }
            }
        }
}

// ---------------- RoPE ----------------
__global__ __launch_bounds__(256) void rope_table()
{
    int idx = blockIdx.x * blockDim.x + threadIdx.x;
    if (idx >= S_ * 64) return;
    int i = idx & 63;
    int s = idx >> 6;
    double inv = pow(10000.0, -(double)(2 * i) / 128.0);
    double ph  = (double)s * inv;
    g_cos[idx] = (float)cos(ph);
    g_sin[idx] = (float)sin(ph);
}

__global__ __launch_bounds__(256) void rope_apply()
{
    int idx = blockIdx.x * blockDim.x + threadIdx.x;  // B*H*S*64 threads
    int i  = idx & 63;
    int s  = (idx >> 6) & (S_ - 1);
    int bh = idx >> 17;                                // 64*S_ = 2^17
    float c  = g_cos[(s << 6) + i];
    float sn = g_sin[(s << 6) + i];
    size_t base = ((size_t)bh * S_ + s) << 7;
    float q1 = g_q[base + i], q2 = g_q[base + 64 + i];
    g_q[base + i]      = q1 * c - q2 * sn;
    g_q[base + 64 + i] = q2 * c + q1 * sn;
    float k1 = g_k[base + i], k2 = g_k[base + 64 + i];
    g_k[base + i]      = k1 * c - k2 * sn;
    g_k[base + 64 + i] = k2 * c + k1 * sn;
}

// ---------------- causal flash attention ----------------
#define BR 64
#define BC 64
#define SP 132     // padded row stride for Q/K/V tiles (132 floats)
#define PSP 68     // padded row stride for P tile
#define ATTN_SMEM ((3*BR*SP + BR*PSP) * 4)

__global__ __launch_bounds__(256) void attn_kernel(
    const float* __restrict__ gq, const float* __restrict__ gk,
    const float* __restrict__ gv, float* __restrict__ gout)
{
    extern __shared__ float smx[];
    float* Qs = smx;
    float* Ks = Qs + BR * SP;
    float* Vs = Ks + BC * SP;
    float* Ps = Vs + BC * SP;

    const int qt = blockIdx.x;   // 0..31 query tile
    const int bh = blockIdx.y;   // 0..31
    const int b  = bh >> 4, h = bh & 15;
    const int tid = threadIdx.x;
    const int tr = tid >> 4, tc = tid & 15;
    const float scale = 0.08838834764831845f;  // 1/sqrt(128)

    const float* qg = gq + ((size_t)bh * S_ + (size_t)qt * BR) * DK_;
    for (int i = tid; i < BR * 32; i += 256) {
        int r = i >> 5, c4 = (i & 31) << 2;
        *(float4*)(Qs + r * SP + c4) = *(const float4*)(qg + (r << 7) + c4);
    }

    float acc[4][8];
#pragma unroll
    for (int ri = 0; ri < 4; ri++)
#pragma unroll
        for (int j = 0; j < 8; j++) acc[ri][j] = 0.f;
    float m_i[4], l_i[4];
#pragma unroll
    for (int ri = 0; ri < 4; ri++) { m_i[ri] = -1e30f; l_i[ri] = 0.f; }

    const int nblk = qt + 1;
    for (int jb = 0; jb < nblk; jb++) {
        __syncthreads();  // previous iter done with Ks/Vs/Ps (and Qs after first load)
        const float* kg = gk + ((size_t)bh * S_ + (size_t)jb * BC) * DK_;
        const float* vg = gv + ((size_t)bh * S_ + (size_t)jb * BC) * DK_;
        for (int i = tid; i < BC * 32; i += 256) {
            int r = i >> 5, c4 = (i & 31) << 2;
            *(float4*)(Ks + r * SP + c4) = *(const float4*)(kg + (r << 7) + c4);
            *(float4*)(Vs + r * SP + c4) = *(const float4*)(vg + (r << 7) + c4);
        }
        __syncthreads();

        // S = Q K^T  (4x4 per thread)
        float sv[4][4];
#pragma unroll
        for (int ri = 0; ri < 4; ri++)
#pragma unroll
            for (int ci = 0; ci < 4; ci++) sv[ri][ci] = 0.f;
#pragma unroll 8
        for (int k0 = 0; k0 < DK_; k0 += 4) {
            float4 qv[4], kv[4];
#pragma unroll
            for (int ri = 0; ri < 4; ri++)
                qv[ri] = *(const float4*)(Qs + (tr*4 + ri) * SP + k0);
#pragma unroll
            for (int ci = 0; ci < 4; ci++)
                kv[ci] = *(const float4*)(Ks + (tc*4 + ci) * SP + k0);
#pragma unroll
            for (int ri = 0; ri < 4; ri++)
#pragma unroll
                for (int ci = 0; ci < 4; ci++) {
                    sv[ri][ci] = fmaf(qv[ri].x, kv[ci].x, sv[ri][ci]);
                    sv[ri][ci] = fmaf(qv[ri].y, kv[ci].y, sv[ri][ci]);
                    sv[ri][ci] = fmaf(qv[ri].z, kv[ci].z, sv[ri][ci]);
                    sv[ri][ci] = fmaf(qv[ri].w, kv[ci].w, sv[ri][ci]);
                }
        }

        const int rg0 = qt * BR + tr * 4;
        const int cg0 = jb * BC + tc * 4;
#pragma unroll
        for (int ri = 0; ri < 4; ri++) {
#pragma unroll
            for (int ci = 0; ci < 4; ci++) {
                float x = sv[ri][ci] * scale;
                if (cg0 + ci > rg0 + ri) x = -1e30f;   // causal mask
                sv[ri][ci] = x;
            }
            float rm = fmaxf(fmaxf(sv[ri][0], sv[ri][1]), fmaxf(sv[ri][2], sv[ri][3]));
#pragma unroll
            for (int o = 8; o >= 1; o >>= 1)
                rm = fmaxf(rm, __shfl_xor_sync(0xffffffffu, rm, o));
            float mnew = fmaxf(m_i[ri], rm);
            float alph = expf(m_i[ri] - mnew);
            m_i[ri] = mnew;
            float rs = 0.f;
#pragma unroll
            for (int ci = 0; ci < 4; ci++) {
                float p = expf(sv[ri][ci] - mnew);
                sv[ri][ci] = p;
                rs += p;
            }
#pragma unroll
            for (int o = 8; o >= 1; o >>= 1)
                rs += __shfl_xor_sync(0xffffffffu, rs, o);
            l_i[ri] = l_i[ri] * alph + rs;
#pragma unroll
            for (int j = 0; j < 8; j++) acc[ri][j] *= alph;
#pragma unroll
            for (int ci = 0; ci < 4; ci++)
                Ps[(tr*4 + ri) * PSP + tc*4 + ci] = sv[ri][ci];
        }
        __syncthreads();

        // O += P V   (thread owns rows tr*4..+3, cols tc*8..+7)
#pragma unroll 4
        for (int c = 0; c < BC; c++) {
            float4 v0 = *(const float4*)(Vs + c * SP + tc * 8);
            float4 v1 = *(const float4*)(Vs + c * SP + tc * 8 + 4);
#pragma unroll
            for (int ri = 0; ri < 4; ri++) {
                float p = Ps[(tr*4 + ri) * PSP + c];
                acc[ri][0] = fmaf(p, v0.x, acc[ri][0]);
                acc[ri][1] = fmaf(p, v0.y, acc[ri][1]);
                acc[ri][2] = fmaf(p, v0.z, acc[ri][2]);
                acc[ri][3] = fmaf(p, v0.w, acc[ri][3]);
                acc[ri][4] = fmaf(p, v1.x, acc[ri][4]);
                acc[ri][5] = fmaf(p, v1.y, acc[ri][5]);
                acc[ri][6] = fmaf(p, v1.z, acc[ri][6]);
                acc[ri][7] = fmaf(p, v1.w, acc[ri][7]);
            }
        }
    }

    // epilogue: O /= l, write to [B,S,D] with col = h*128 + d
#pragma unroll
    for (int ri = 0; ri < 4; ri++) {
        float inv = 1.f / l_i[ri];
        int srow = qt * BR + tr * 4 + ri;
        float* o = gout + ((size_t)b * S_ + srow) * D_ + (h << 7) + tc * 8;
        float4 r0, r1;
        r0.x = acc[ri][0]*inv; r0.y = acc[ri][1]*inv; r0.z = acc[ri][2]*inv; r0.w = acc[ri][3]*inv;
        r1.x = acc[ri][4]*inv; r1.y = acc[ri][5]*inv; r1.z = acc[ri][6]*inv; r1.w = acc[ri][7]*inv;
        *(float4*)(o)     = r0;
        *(float4*)(o + 4) = r1;
    }
}

// ---------------- launch ----------------
extern "C" void kernel_launch(void* const* d_in, const int* in_sizes, int n_in,
                              void* d_out, int out_size)
{
    const float* query = (const float*)d_in[0];
    const float* key   = (const float*)d_in[1];
    const float* value = (const float*)d_in[2];
    // d_in[3] = mask (causal tril) — hardcoded in attn kernel
    const float* wq = (const float*)d_in[4];
    const float* bq = (const float*)d_in[5];
    const float* wk = (const float*)d_in[6];
    const float* bk = (const float*)d_in[7];
    const float* wv = (const float*)d_in[8];
    const float* bv = (const float*)d_in[9];
    const float* wo = (const float*)d_in[10];
    const float* bo = (const float*)d_in[11];
    float* out = (float*)d_out;

    float *q_s, *k_s, *v_s, *attn_s;
    cudaGetSymbolAddress((void**)&q_s, g_q);
    cudaGetSymbolAddress((void**)&k_s, g_k);
    cudaGetSymbolAddress((void**)&v_s, g_v);
    cudaGetSymbolAddress((void**)&attn_s, g_attn);

    cudaFuncSetAttribute(attn_kernel,
                         cudaFuncAttributeMaxDynamicSharedMemorySize, ATTN_SMEM);

    dim3 ggrid(D_ / 128, M_ / 128);  // (16, 32)
    sgemm_tn<<<ggrid, 256>>>(query, wq, bq, q_s, D_, 1);
    sgemm_tn<<<ggrid, 256>>>(key,   wk, bk, k_s, D_, 1);
    sgemm_tn<<<ggrid, 256>>>(value, wv, bv, v_s, D_, 1);

    rope_table<<<(S_ * 64) / 256, 256>>>();
    rope_apply<<<(B_ * H_ * S_ * 64) / 256, 256>>>();

    attn_kernel<<<dim3(S_ / BR, B_ * H_), 256, ATTN_SMEM>>>(q_s, k_s, v_s, attn_s);

    sgemm_tn<<<ggrid, 256>>>(attn_s, wo, bo, out, D_, 0);
}

// round 4
// speedup vs baseline: 1.5851x; 1.5851x over previous
#include <cuda_runtime.h>
#include <cuda_bf16.h>
#include <math.h>
#include <stdint.h>

#define B_  2
#define S_  2048
#define D_  2048
#define H_  16
#define DK_ 128
#define M_  (B_*S_)   // 4096
#define K3_ 6144      // 3*D_ (bf16x3 split concat)
#define NCH 96        // K3_/64 chunks

// ---------------- scratch (device globals; no allocs allowed) ----------------
__device__ __nv_bfloat16 g_acat[M_*K3_];   // 48MB  activation cat [hi|hi|lo]
__device__ __nv_bfloat16 g_wcat[D_*K3_];   // 24MB  weight cat     [hi|lo|hi]
__device__ float g_q[B_*H_*S_*DK_];
__device__ float g_k[B_*H_*S_*DK_];
__device__ float g_v[B_*H_*S_*DK_];
__device__ float g_attn[B_*S_*D_];
__device__ float g_cos[S_*64];
__device__ float g_sin[S_*64];

__device__ __forceinline__ uint32_t smem_u32(const void* p) {
    uint32_t a;
    asm("{ .reg .u64 t; cvta.to.shared.u64 t, %1; cvt.u32.u64 %0, t; }" : "=r"(a) : "l"(p));
    return a;
}

// ---------------- bf16 split: out rows of 6144 = [hi | s1 | s2] ----------------
// act=1: s1=hi, s2=lo (activations).  act=0: s1=lo, s2=hi (weights).
__global__ __launch_bounds__(256) void split_kernel(
    const float* __restrict__ x, __nv_bfloat16* __restrict__ out, int nelem, int act)
{
    int i4 = (blockIdx.x * 256 + threadIdx.x) * 4;
    if (i4 >= nelem) return;
    int r = i4 >> 11, c = i4 & 2047;
    float4 v = *(const float4*)(x + i4);
    __nv_bfloat16 h0 = __float2bfloat16(v.x), h1 = __float2bfloat16(v.y);
    __nv_bfloat16 h2 = __float2bfloat16(v.z), h3 = __float2bfloat16(v.w);
    __nv_bfloat16 l0 = __float2bfloat16(v.x - __bfloat162float(h0));
    __nv_bfloat16 l1 = __float2bfloat16(v.y - __bfloat162float(h1));
    __nv_bfloat16 l2 = __float2bfloat16(v.z - __bfloat162float(h2));
    __nv_bfloat16 l3 = __float2bfloat16(v.w - __bfloat162float(h3));
    __nv_bfloat162 H01, H23, L01, L23;
    H01.x = h0; H01.y = h1; H23.x = h2; H23.y = h3;
    L01.x = l0; L01.y = l1; L23.x = l2; L23.y = l3;
    __nv_bfloat16* row = out + (size_t)r * K3_ + c;
    *(__nv_bfloat162*)(row)     = H01;
    *(__nv_bfloat162*)(row + 2) = H23;
    if (act) {
        *(__nv_bfloat162*)(row + 2048)     = H01;
        *(__nv_bfloat162*)(row + 2048 + 2) = H23;
        *(__nv_bfloat162*)(row + 4096)     = L01;
        *(__nv_bfloat162*)(row + 4096 + 2) = L23;
    } else {
        *(__nv_bfloat162*)(row + 2048)     = L01;
        *(__nv_bfloat162*)(row + 2048 + 2) = L23;
        *(__nv_bfloat162*)(row + 4096)     = H01;
        *(__nv_bfloat162*)(row + 4096 + 2) = H23;
    }
}

// ---------------- mma.sync GEMM: C[m,n] = sum_k Acat[m,k]*Wcat[n,k] + bias[n] --
// 128x128 tile, 256 thr = 8 warps (2x4), warp tile 64x32, K-chunk 64, dbl-buffer cp.async.
#define LDA 72                     // padded smem row stride (elements)
#define TILE_E (128*LDA)           // elems per tile buffer
#define GEMM_SMEM (4*TILE_E*2)     // 2 stages * (A+B) * 2B = 73728 B

__global__ __launch_bounds__(256, 2) void gemm_mma(
    const __nv_bfloat16* __restrict__ A, const __nv_bfloat16* __restrict__ Wt,
    const float* __restrict__ bias, float* __restrict__ C, int headed)
{
    extern __shared__ __nv_bfloat16 sm[];
    __nv_bfloat16* AsB = sm;                // [2][128][LDA]
    __nv_bfloat16* BsB = sm + 2 * TILE_E;
    const int tid = threadIdx.x;
    const int lane = tid & 31, w = tid >> 5;
    const int wm = (w >> 2) << 6;           // 0 / 64
    const int wn = (w & 3) << 5;            // 0,32,64,96
    const int m0 = blockIdx.y << 7, n0 = blockIdx.x << 7;

    const __nv_bfloat16* Ag = A  + (size_t)m0 * K3_;
    const __nv_bfloat16* Wg = Wt + (size_t)n0 * K3_;

    float acc[4][4][4];
#pragma unroll
    for (int mi = 0; mi < 4; mi++)
#pragma unroll
        for (int ni = 0; ni < 4; ni++)
#pragma unroll
            for (int j = 0; j < 4; j++) acc[mi][ni][j] = 0.f;

    // load-chunk: 128 rows x 64 elems per tile, 16B per cp.async, 4+4 per thread
    const int lrow = tid >> 3, lc8 = (tid & 7) << 3;
#define LOAD_CHUNK(stage, chunk) do {                                            \
    __nv_bfloat16* as = AsB + (stage) * TILE_E;                                  \
    __nv_bfloat16* bs = BsB + (stage) * TILE_E;                                  \
    const __nv_bfloat16* Ac = Ag + (size_t)(chunk) * 64;                         \
    const __nv_bfloat16* Wc = Wg + (size_t)(chunk) * 64;                         \
    _Pragma("unroll")                                                            \
    for (int i = 0; i < 4; i++) {                                                \
        int row = lrow + i * 32;                                                 \
        uint32_t sa = smem_u32(as + row * LDA + lc8);                            \
        uint32_t sbp = smem_u32(bs + row * LDA + lc8);                           \
        asm volatile("cp.async.cg.shared.global [%0], [%1], 16;"                 \
                     :: "r"(sa), "l"(Ac + (size_t)row * K3_ + lc8));             \
        asm volatile("cp.async.cg.shared.global [%0], [%1], 16;"                 \
                     :: "r"(sbp), "l"(Wc + (size_t)row * K3_ + lc8));            \
    }                                                                            \
    asm volatile("cp.async.commit_group;" ::: "memory");                         \
} while (0)

    LOAD_CHUNK(0, 0);

    for (int c = 0; c < NCH; c++) {
        int s = c & 1;
        if (c + 1 < NCH) {
            LOAD_CHUNK(1 - s, c + 1);
            asm volatile("cp.async.wait_group 1;" ::: "memory");
        } else {
            asm volatile("cp.async.wait_group 0;" ::: "memory");
        }
        __syncthreads();

        const __nv_bfloat16* as = AsB + s * TILE_E;
        const __nv_bfloat16* bs = BsB + s * TILE_E;
#pragma unroll
        for (int ks = 0; ks < 4; ks++) {
            const int kc = ks << 4;
            uint32_t a[4][4];
#pragma unroll
            for (int mi = 0; mi < 4; mi++) {
                int r = wm + (mi << 4) + (lane & 15);
                int cc = kc + ((lane >> 4) << 3);
                uint32_t ad = smem_u32(as + r * LDA + cc);
                asm volatile("ldmatrix.sync.aligned.m8n8.x4.shared.b16 {%0,%1,%2,%3}, [%4];"
                    : "=r"(a[mi][0]), "=r"(a[mi][1]), "=r"(a[mi][2]), "=r"(a[mi][3]) : "r"(ad));
            }
            uint32_t b[4][2];
#pragma unroll
            for (int nb = 0; nb < 2; nb++) {
                int r = wn + (nb << 4) + (lane & 7) + (((lane >> 4) & 1) << 3);
                int cc = kc + (((lane >> 3) & 1) << 3);
                uint32_t ad = smem_u32(bs + r * LDA + cc);
                asm volatile("ldmatrix.sync.aligned.m8n8.x4.shared.b16 {%0,%1,%2,%3}, [%4];"
                    : "=r"(b[nb*2][0]), "=r"(b[nb*2][1]), "=r"(b[nb*2+1][0]), "=r"(b[nb*2+1][1])
                    : "r"(ad));
            }
#pragma unroll
            for (int mi = 0; mi < 4; mi++)
#pragma unroll
                for (int ni = 0; ni < 4; ni++)
                    asm volatile("mma.sync.aligned.m16n8k16.row.col.f32.bf16.bf16.f32 "
                        "{%0,%1,%2,%3}, {%4,%5,%6,%7}, {%8,%9}, {%0,%1,%2,%3};"
                        : "+f"(acc[mi][ni][0]), "+f"(acc[mi][ni][1]),
                          "+f"(acc[mi][ni][2]), "+f"(acc[mi][ni][3])
                        : "r"(a[mi][0]), "r"(a[mi][1]), "r"(a[mi][2]), "r"(a[mi][3]),
                          "r"(b[ni][0]), "r"(b[ni][1]));
        }
        __syncthreads();
    }

    // epilogue: thread holds (m, n) = (wm+mi*16+lane/4 [+8], wn+ni*8+(lane%4)*2 [,+1])
#pragma unroll
    for (int mi = 0; mi < 4; mi++) {
#pragma unroll
        for (int half = 0; half < 2; half++) {
            int m = m0 + wm + (mi << 4) + (lane >> 2) + (half << 3);
            float* dst;
#pragma unroll
            for (int ni = 0; ni < 4; ni++) {
                int n = n0 + wn + (ni << 3) + ((lane & 3) << 1);
                float2 o;
                o.x = acc[mi][ni][half*2+0] + bias[n];
                o.y = acc[mi][ni][half*2+1] + bias[n+1];
                if (headed) {
                    int b = m >> 11, sidx = m & (S_ - 1), h = n >> 7, dk = n & (DK_ - 1);
                    dst = C + ((((size_t)b * H_ + h) * S_ + sidx) << 7) + dk;
                } else {
                    dst = C + (size_t)m * D_ + n;
                }
                *(float2*)dst = o;
            }
        }
    }
}

// ---------------- RoPE ----------------
__global__ __launch_bounds__(256) void rope_table()
{
    int idx = blockIdx.x * blockDim.x + threadIdx.x;
    if (idx >= S_ * 64) return;
    int i = idx & 63;
    int s = idx >> 6;
    double inv = pow(10000.0, -(double)(2 * i) / 128.0);
    double ph  = (double)s * inv;
    g_cos[idx] = (float)cos(ph);
    g_sin[idx] = (float)sin(ph);
}

__global__ __launch_bounds__(256) void rope_apply()
{
    int idx = blockIdx.x * blockDim.x + threadIdx.x;  // B*H*S*64 threads
    int i  = idx & 63;
    int s  = (idx >> 6) & (S_ - 1);
    int bh = idx >> 17;
    float c  = g_cos[(s << 6) + i];
    float sn = g_sin[(s << 6) + i];
    size_t base = ((size_t)bh * S_ + s) << 7;
    float q1 = g_q[base + i], q2 = g_q[base + 64 + i];
    g_q[base + i]      = q1 * c - q2 * sn;
    g_q[base + 64 + i] = q2 * c + q1 * sn;
    float k1 = g_k[base + i], k2 = g_k[base + 64 + i];
    g_k[base + i]      = k1 * c - k2 * sn;
    g_k[base + 64 + i] = k2 * c + k1 * sn;
}

// ---------------- causal flash attention (fp32) ----------------
#define BR 64
#define BC 64
#define SP 132
#define PSP 68
#define ATTN_SMEM ((3*BR*SP + BR*PSP) * 4)

__global__ __launch_bounds__(256) void attn_kernel(
    const float* __restrict__ gq, const float* __restrict__ gk,
    const float* __restrict__ gv, float* __restrict__ gout)
{
    extern __shared__ float smx[];
    float* Qs = smx;
    float* Ks = Qs + BR * SP;
    float* Vs = Ks + BC * SP;
    float* Ps = Vs + BC * SP;

    const int qt = blockIdx.x;
    const int bh = blockIdx.y;
    const int b  = bh >> 4, h = bh & 15;
    const int tid = threadIdx.x;
    const int tr = tid >> 4, tc = tid & 15;
    const float scale = 0.08838834764831845f;

    const float* qg = gq + ((size_t)bh * S_ + (size_t)qt * BR) * DK_;
    for (int i = tid; i < BR * 32; i += 256) {
        int r = i >> 5, c4 = (i & 31) << 2;
        *(float4*)(Qs + r * SP + c4) = *(const float4*)(qg + (r << 7) + c4);
    }

    float acc[4][8];
#pragma unroll
    for (int ri = 0; ri < 4; ri++)
#pragma unroll
        for (int j = 0; j < 8; j++) acc[ri][j] = 0.f;
    float m_i[4], l_i[4];
#pragma unroll
    for (int ri = 0; ri < 4; ri++) { m_i[ri] = -1e30f; l_i[ri] = 0.f; }

    const int nblk = qt + 1;
    for (int jb = 0; jb < nblk; jb++) {
        __syncthreads();
        const float* kg = gk + ((size_t)bh * S_ + (size_t)jb * BC) * DK_;
        const float* vg = gv + ((size_t)bh * S_ + (size_t)jb * BC) * DK_;
        for (int i = tid; i < BC * 32; i += 256) {
            int r = i >> 5, c4 = (i & 31) << 2;
            *(float4*)(Ks + r * SP + c4) = *(const float4*)(kg + (r << 7) + c4);
            *(float4*)(Vs + r * SP + c4) = *(const float4*)(vg + (r << 7) + c4);
        }
        __syncthreads();

        float sv[4][4];
#pragma unroll
        for (int ri = 0; ri < 4; ri++)
#pragma unroll
            for (int ci = 0; ci < 4; ci++) sv[ri][ci] = 0.f;
#pragma unroll 8
        for (int k0 = 0; k0 < DK_; k0 += 4) {
            float4 qv[4], kv[4];
#pragma unroll
            for (int ri = 0; ri < 4; ri++)
                qv[ri] = *(const float4*)(Qs + (tr*4 + ri) * SP + k0);
#pragma unroll
            for (int ci = 0; ci < 4; ci++)
                kv[ci] = *(const float4*)(Ks + (tc*4 + ci) * SP + k0);
#pragma unroll
            for (int ri = 0; ri < 4; ri++)
#pragma unroll
                for (int ci = 0; ci < 4; ci++) {
                    sv[ri][ci] = fmaf(qv[ri].x, kv[ci].x, sv[ri][ci]);
                    sv[ri][ci] = fmaf(qv[ri].y, kv[ci].y, sv[ri][ci]);
                    sv[ri][ci] = fmaf(qv[ri].z, kv[ci].z, sv[ri][ci]);
                    sv[ri][ci] = fmaf(qv[ri].w, kv[ci].w, sv[ri][ci]);
                }
        }

        const int rg0 = qt * BR + tr * 4;
        const int cg0 = jb * BC + tc * 4;
#pragma unroll
        for (int ri = 0; ri < 4; ri++) {
#pragma unroll
            for (int ci = 0; ci < 4; ci++) {
                float x = sv[ri][ci] * scale;
                if (cg0 + ci > rg0 + ri) x = -1e30f;
                sv[ri][ci] = x;
            }
            float rm = fmaxf(fmaxf(sv[ri][0], sv[ri][1]), fmaxf(sv[ri][2], sv[ri][3]));
#pragma unroll
            for (int o = 8; o >= 1; o >>= 1)
                rm = fmaxf(rm, __shfl_xor_sync(0xffffffffu, rm, o));
            float mnew = fmaxf(m_i[ri], rm);
            float alph = expf(m_i[ri] - mnew);
            m_i[ri] = mnew;
            float rs = 0.f;
#pragma unroll
            for (int ci = 0; ci < 4; ci++) {
                float p = expf(sv[ri][ci] - mnew);
                sv[ri][ci] = p;
                rs += p;
            }
#pragma unroll
            for (int o = 8; o >= 1; o >>= 1)
                rs += __shfl_xor_sync(0xffffffffu, rs, o);
            l_i[ri] = l_i[ri] * alph + rs;
#pragma unroll
            for (int j = 0; j < 8; j++) acc[ri][j] *= alph;
#pragma unroll
            for (int ci = 0; ci < 4; ci++)
                Ps[(tr*4 + ri) * PSP + tc*4 + ci] = sv[ri][ci];
        }
        __syncthreads();

#pragma unroll 4
        for (int c = 0; c < BC; c++) {
            float4 v0 = *(const float4*)(Vs + c * SP + tc * 8);
            float4 v1 = *(const float4*)(Vs + c * SP + tc * 8 + 4);
#pragma unroll
            for (int ri = 0; ri < 4; ri++) {
                float p = Ps[(tr*4 + ri) * PSP + c];
                acc[ri][0] = fmaf(p, v0.x, acc[ri][0]);
                acc[ri][1] = fmaf(p, v0.y, acc[ri][1]);
                acc[ri][2] = fmaf(p, v0.z, acc[ri][2]);
                acc[ri][3] = fmaf(p, v0.w, acc[ri][3]);
                acc[ri][4] = fmaf(p, v1.x, acc[ri][4]);
                acc[ri][5] = fmaf(p, v1.y, acc[ri][5]);
                acc[ri][6] = fmaf(p, v1.z, acc[ri][6]);
                acc[ri][7] = fmaf(p, v1.w, acc[ri][7]);
            }
        }
    }

#pragma unroll
    for (int ri = 0; ri < 4; ri++) {
        float inv = 1.f / l_i[ri];
        int srow = qt * BR + tr * 4 + ri;
        float* o = gout + ((size_t)b * S_ + srow) * D_ + (h << 7) + tc * 8;
        float4 r0, r1;
        r0.x = acc[ri][0]*inv; r0.y = acc[ri][1]*inv; r0.z = acc[ri][2]*inv; r0.w = acc[ri][3]*inv;
        r1.x = acc[ri][4]*inv; r1.y = acc[ri][5]*inv; r1.z = acc[ri][6]*inv; r1.w = acc[ri][7]*inv;
        *(float4*)(o)     = r0;
        *(float4*)(o + 4) = r1;
    }
}

// ---------------- launch ----------------
extern "C" void kernel_launch(void* const* d_in, const int* in_sizes, int n_in,
                              void* d_out, int out_size)
{
    const float* query = (const float*)d_in[0];
    const float* key   = (const float*)d_in[1];
    const float* value = (const float*)d_in[2];
    const float* wq = (const float*)d_in[4];
    const float* bq = (const float*)d_in[5];
    const float* wk = (const float*)d_in[6];
    const float* bk = (const float*)d_in[7];
    const float* wv = (const float*)d_in[8];
    const float* bv = (const float*)d_in[9];
    const float* wo = (const float*)d_in[10];
    const float* bo = (const float*)d_in[11];
    float* out = (float*)d_out;

    float *q_s, *k_s, *v_s, *attn_s;
    __nv_bfloat16 *acat, *wcat;
    cudaGetSymbolAddress((void**)&q_s, g_q);
    cudaGetSymbolAddress((void**)&k_s, g_k);
    cudaGetSymbolAddress((void**)&v_s, g_v);
    cudaGetSymbolAddress((void**)&attn_s, g_attn);
    cudaGetSymbolAddress((void**)&acat, g_acat);
    cudaGetSymbolAddress((void**)&wcat, g_wcat);

    cudaFuncSetAttribute(attn_kernel, cudaFuncAttributeMaxDynamicSharedMemorySize, ATTN_SMEM);
    cudaFuncSetAttribute(gemm_mma, cudaFuncAttributeMaxDynamicSharedMemorySize, GEMM_SMEM);

    const int wgrid = (D_ * D_ / 4 + 255) / 256;
    const int agrid = (M_ * D_ / 4 + 255) / 256;
    dim3 ggrid(D_ / 128, M_ / 128);                // (16, 32)

    // Q projection
    split_kernel<<<agrid, 256>>>(query, acat, M_ * D_, 1);
    split_kernel<<<wgrid, 256>>>(wq, wcat, D_ * D_, 0);
    gemm_mma<<<ggrid, 256, GEMM_SMEM>>>(acat, wcat, bq, q_s, 1);
    // K projection
    split_kernel<<<agrid, 256>>>(key, acat, M_ * D_, 1);
    split_kernel<<<wgrid, 256>>>(wk, wcat, D_ * D_, 0);
    gemm_mma<<<ggrid, 256, GEMM_SMEM>>>(acat, wcat, bk, k_s, 1);
    // V projection
    split_kernel<<<agrid, 256>>>(value, acat, M_ * D_, 1);
    split_kernel<<<wgrid, 256>>>(wv, wcat, D_ * D_, 0);
    gemm_mma<<<ggrid, 256, GEMM_SMEM>>>(acat, wcat, bv, v_s, 1);

    rope_table<<<(S_ * 64) / 256, 256>>>();
    rope_apply<<<(B_ * H_ * S_ * 64) / 256, 256>>>();

    attn_kernel<<<dim3(S_ / BR, B_ * H_), 256, ATTN_SMEM>>>(q_s, k_s, v_s, attn_s);

    // Output projection
    split_kernel<<<agrid, 256>>>(attn_s, acat, M_ * D_, 1);
    split_kernel<<<wgrid, 256>>>(wo, wcat, D_ * D_, 0);
    gemm_mma<<<ggrid, 256, GEMM_SMEM>>>(acat, wcat, bo, out, 0);
}

// round 5
// speedup vs baseline: 1.5938x; 1.0055x over previous
#include <cuda_runtime.h>
#include <cuda_bf16.h>
#include <math.h>
#include <stdint.h>

#define B_  2
#define S_  2048
#define D_  2048
#define H_  16
#define DK_ 128
#define M_  (B_*S_)   // 4096
#define K3_ 6144      // 3*D_ (bf16x3 split concat)
#define NCH 96        // K3_/64 chunks

// ---------------- scratch (device globals; no allocs allowed) ----------------
__device__ __nv_bfloat16 g_acat[M_*K3_];   // 48MB  activation cat [hi|hi|lo]
__device__ __nv_bfloat16 g_wcat[D_*K3_];   // 24MB  weight cat     [hi|lo|hi]
__device__ float g_q[B_*H_*S_*DK_];
__device__ float g_k[B_*H_*S_*DK_];
__device__ float g_v[B_*H_*S_*DK_];
__device__ float g_attn[B_*S_*D_];
__device__ float g_cos[S_*64];
__device__ float g_sin[S_*64];

__device__ __forceinline__ uint32_t smem_u32(const void* p) {
    uint32_t a;
    asm("{ .reg .u64 t; cvta.to.shared.u64 t, %1; cvt.u32.u64 %0, t; }" : "=r"(a) : "l"(p));
    return a;
}

// ---------------- bf16 split: out rows of 6144 = [hi | s1 | s2] ----------------
// act=1: s1=hi, s2=lo (activations).  act=0: s1=lo, s2=hi (weights).
__global__ __launch_bounds__(256) void split_kernel(
    const float* __restrict__ x, __nv_bfloat16* __restrict__ out, int nelem, int act)
{
    int i4 = (blockIdx.x * 256 + threadIdx.x) * 4;
    if (i4 >= nelem) return;
    int r = i4 >> 11, c = i4 & 2047;
    float4 v = *(const float4*)(x + i4);
    __nv_bfloat16 h0 = __float2bfloat16(v.x), h1 = __float2bfloat16(v.y);
    __nv_bfloat16 h2 = __float2bfloat16(v.z), h3 = __float2bfloat16(v.w);
    __nv_bfloat16 l0 = __float2bfloat16(v.x - __bfloat162float(h0));
    __nv_bfloat16 l1 = __float2bfloat16(v.y - __bfloat162float(h1));
    __nv_bfloat16 l2 = __float2bfloat16(v.z - __bfloat162float(h2));
    __nv_bfloat16 l3 = __float2bfloat16(v.w - __bfloat162float(h3));
    __nv_bfloat162 H01, H23, L01, L23;
    H01.x = h0; H01.y = h1; H23.x = h2; H23.y = h3;
    L01.x = l0; L01.y = l1; L23.x = l2; L23.y = l3;
    __nv_bfloat16* row = out + (size_t)r * K3_ + c;
    *(__nv_bfloat162*)(row)     = H01;
    *(__nv_bfloat162*)(row + 2) = H23;
    if (act) {
        *(__nv_bfloat162*)(row + 2048)     = H01;
        *(__nv_bfloat162*)(row + 2048 + 2) = H23;
        *(__nv_bfloat162*)(row + 4096)     = L01;
        *(__nv_bfloat162*)(row + 4096 + 2) = L23;
    } else {
        *(__nv_bfloat162*)(row + 2048)     = L01;
        *(__nv_bfloat162*)(row + 2048 + 2) = L23;
        *(__nv_bfloat162*)(row + 4096)     = H01;
        *(__nv_bfloat162*)(row + 4096 + 2) = H23;
    }
}

// ---------------- mma.sync GEMM: C[m,n] = sum_k Acat[m,k]*Wcat[n,k] + bias[n] --
// 128x128 tile, 256 thr = 8 warps (2x4), warp tile 64x32, K-chunk 64,
// 3-stage cp.async ring, ONE __syncthreads per chunk.
#define LDA 72                     // padded smem row stride (elements)
#define TILE_E (128*LDA)           // elems per tile buffer
#define NSTAGE 3
#define GEMM_SMEM (NSTAGE*2*TILE_E*2)   // 3 stages * (A+B) * 2B = 110592 B

__global__ __launch_bounds__(256, 2) void gemm_mma(
    const __nv_bfloat16* __restrict__ A, const __nv_bfloat16* __restrict__ Wt,
    const float* __restrict__ bias, float* __restrict__ C, int headed)
{
    extern __shared__ __nv_bfloat16 sm[];
    __nv_bfloat16* AsB = sm;                       // [3][128][LDA]
    __nv_bfloat16* BsB = sm + NSTAGE * TILE_E;     // [3][128][LDA]
    const int tid = threadIdx.x;
    const int lane = tid & 31, w = tid >> 5;
    const int wm = (w >> 2) << 6;           // 0 / 64
    const int wn = (w & 3) << 5;            // 0,32,64,96
    const int m0 = blockIdx.y << 7, n0 = blockIdx.x << 7;

    const __nv_bfloat16* Ag = A  + (size_t)m0 * K3_;
    const __nv_bfloat16* Wg = Wt + (size_t)n0 * K3_;

    float acc[4][4][4];
#pragma unroll
    for (int mi = 0; mi < 4; mi++)
#pragma unroll
        for (int ni = 0; ni < 4; ni++)
#pragma unroll
            for (int j = 0; j < 4; j++) acc[mi][ni][j] = 0.f;

    const int lrow = tid >> 3, lc8 = (tid & 7) << 3;
#define LOAD_CHUNK(stage, chunk) do {                                            \
    __nv_bfloat16* as = AsB + (stage) * TILE_E;                                  \
    __nv_bfloat16* bs = BsB + (stage) * TILE_E;                                  \
    const __nv_bfloat16* Ac = Ag + (size_t)(chunk) * 64;                         \
    const __nv_bfloat16* Wc = Wg + (size_t)(chunk) * 64;                         \
    _Pragma("unroll")                                                            \
    for (int i = 0; i < 4; i++) {                                                \
        int row = lrow + i * 32;                                                 \
        uint32_t sa = smem_u32(as + row * LDA + lc8);                            \
        uint32_t sbp = smem_u32(bs + row * LDA + lc8);                           \
        asm volatile("cp.async.cg.shared.global [%0], [%1], 16;"                 \
                     :: "r"(sa), "l"(Ac + (size_t)row * K3_ + lc8));             \
        asm volatile("cp.async.cg.shared.global [%0], [%1], 16;"                 \
                     :: "r"(sbp), "l"(Wc + (size_t)row * K3_ + lc8));            \
    }                                                                            \
    asm volatile("cp.async.commit_group;" ::: "memory");                         \
} while (0)

    LOAD_CHUNK(0, 0);
    LOAD_CHUNK(1, 1);

    for (int c = 0; c < NCH; c++) {
        const int s = c % NSTAGE;
        // wait for chunk c to be resident (pending after wait: at most chunk c+1)
        if (c + 1 < NCH) {
            asm volatile("cp.async.wait_group 1;" ::: "memory");
        } else {
            asm volatile("cp.async.wait_group 0;" ::: "memory");
        }
        __syncthreads();   // all warps done computing chunk c-1 => stage (c+2)%3 free

        if (c + 2 < NCH) LOAD_CHUNK((c + 2) % NSTAGE, c + 2);

        const __nv_bfloat16* as = AsB + s * TILE_E;
        const __nv_bfloat16* bs = BsB + s * TILE_E;
#pragma unroll
        for (int ks = 0; ks < 4; ks++) {
            const int kc = ks << 4;
            uint32_t a[4][4];
#pragma unroll
            for (int mi = 0; mi < 4; mi++) {
                int r = wm + (mi << 4) + (lane & 15);
                int cc = kc + ((lane >> 4) << 3);
                uint32_t ad = smem_u32(as + r * LDA + cc);
                asm volatile("ldmatrix.sync.aligned.m8n8.x4.shared.b16 {%0,%1,%2,%3}, [%4];"
                    : "=r"(a[mi][0]), "=r"(a[mi][1]), "=r"(a[mi][2]), "=r"(a[mi][3]) : "r"(ad));
            }
            uint32_t b[4][2];
#pragma unroll
            for (int nb = 0; nb < 2; nb++) {
                int r = wn + (nb << 4) + (lane & 7) + (((lane >> 4) & 1) << 3);
                int cc = kc + (((lane >> 3) & 1) << 3);
                uint32_t ad = smem_u32(bs + r * LDA + cc);
                asm volatile("ldmatrix.sync.aligned.m8n8.x4.shared.b16 {%0,%1,%2,%3}, [%4];"
                    : "=r"(b[nb*2][0]), "=r"(b[nb*2][1]), "=r"(b[nb*2+1][0]), "=r"(b[nb*2+1][1])
                    : "r"(ad));
            }
#pragma unroll
            for (int mi = 0; mi < 4; mi++)
#pragma unroll
                for (int ni = 0; ni < 4; ni++)
                    asm volatile("mma.sync.aligned.m16n8k16.row.col.f32.bf16.bf16.f32 "
                        "{%0,%1,%2,%3}, {%4,%5,%6,%7}, {%8,%9}, {%0,%1,%2,%3};"
                        : "+f"(acc[mi][ni][0]), "+f"(acc[mi][ni][1]),
                          "+f"(acc[mi][ni][2]), "+f"(acc[mi][ni][3])
                        : "r"(a[mi][0]), "r"(a[mi][1]), "r"(a[mi][2]), "r"(a[mi][3]),
                          "r"(b[ni][0]), "r"(b[ni][1]));
        }
    }

    // epilogue
#pragma unroll
    for (int mi = 0; mi < 4; mi++) {
#pragma unroll
        for (int half = 0; half < 2; half++) {
            int m = m0 + wm + (mi << 4) + (lane >> 2) + (half << 3);
            float* dst;
#pragma unroll
            for (int ni = 0; ni < 4; ni++) {
                int n = n0 + wn + (ni << 3) + ((lane & 3) << 1);
                float2 o;
                o.x = acc[mi][ni][half*2+0] + bias[n];
                o.y = acc[mi][ni][half*2+1] + bias[n+1];
                if (headed) {
                    int b = m >> 11, sidx = m & (S_ - 1), h = n >> 7, dk = n & (DK_ - 1);
                    dst = C + ((((size_t)b * H_ + h) * S_ + sidx) << 7) + dk;
                } else {
                    dst = C + (size_t)m * D_ + n;
                }
                *(float2*)dst = o;
            }
        }
    }
}

// ---------------- RoPE ----------------
__global__ __launch_bounds__(256) void rope_table()
{
    int idx = blockIdx.x * blockDim.x + threadIdx.x;
    if (idx >= S_ * 64) return;
    int i = idx & 63;
    int s = idx >> 6;
    float inv = powf(10000.f, -(float)(2 * i) / 128.f);
    float ph  = (float)s * inv;
    g_cos[idx] = cosf(ph);
    g_sin[idx] = sinf(ph);
}

__global__ __launch_bounds__(256) void rope_apply()
{
    int idx = blockIdx.x * blockDim.x + threadIdx.x;  // B*H*S*64 threads
    int i  = idx & 63;
    int s  = (idx >> 6) & (S_ - 1);
    int bh = idx >> 17;
    float c  = g_cos[(s << 6) + i];
    float sn = g_sin[(s << 6) + i];
    size_t base = ((size_t)bh * S_ + s) << 7;
    float q1 = g_q[base + i], q2 = g_q[base + 64 + i];
    g_q[base + i]      = q1 * c - q2 * sn;
    g_q[base + 64 + i] = q2 * c + q1 * sn;
    float k1 = g_k[base + i], k2 = g_k[base + 64 + i];
    g_k[base + i]      = k1 * c - k2 * sn;
    g_k[base + 64 + i] = k2 * c + k1 * sn;
}

// ---------------- causal flash attention (fp32) ----------------
#define BR 64
#define BC 64
#define SP 132
#define PSP 68
#define ATTN_SMEM ((3*BR*SP + BR*PSP) * 4)

__global__ __launch_bounds__(256) void attn_kernel(
    const float* __restrict__ gq, const float* __restrict__ gk,
    const float* __restrict__ gv, float* __restrict__ gout)
{
    extern __shared__ float smx[];
    float* Qs = smx;
    float* Ks = Qs + BR * SP;
    float* Vs = Ks + BC * SP;
    float* Ps = Vs + BC * SP;

    const int qt = blockIdx.x;
    const int bh = blockIdx.y;
    const int b  = bh >> 4, h = bh & 15;
    const int tid = threadIdx.x;
    const int tr = tid >> 4, tc = tid & 15;
    const float scale = 0.08838834764831845f;

    const float* qg = gq + ((size_t)bh * S_ + (size_t)qt * BR) * DK_;
    for (int i = tid; i < BR * 32; i += 256) {
        int r = i >> 5, c4 = (i & 31) << 2;
        *(float4*)(Qs + r * SP + c4) = *(const float4*)(qg + (r << 7) + c4);
    }

    float acc[4][8];
#pragma unroll
    for (int ri = 0; ri < 4; ri++)
#pragma unroll
        for (int j = 0; j < 8; j++) acc[ri][j] = 0.f;
    float m_i[4], l_i[4];
#pragma unroll
    for (int ri = 0; ri < 4; ri++) { m_i[ri] = -1e30f; l_i[ri] = 0.f; }

    const int nblk = qt + 1;
    for (int jb = 0; jb < nblk; jb++) {
        __syncthreads();
        const float* kg = gk + ((size_t)bh * S_ + (size_t)jb * BC) * DK_;
        const float* vg = gv + ((size_t)bh * S_ + (size_t)jb * BC) * DK_;
        for (int i = tid; i < BC * 32; i += 256) {
            int r = i >> 5, c4 = (i & 31) << 2;
            *(float4*)(Ks + r * SP + c4) = *(const float4*)(kg + (r << 7) + c4);
            *(float4*)(Vs + r * SP + c4) = *(const float4*)(vg + (r << 7) + c4);
        }
        __syncthreads();

        float sv[4][4];
#pragma unroll
        for (int ri = 0; ri < 4; ri++)
#pragma unroll
            for (int ci = 0; ci < 4; ci++) sv[ri][ci] = 0.f;
#pragma unroll 8
        for (int k0 = 0; k0 < DK_; k0 += 4) {
            float4 qv[4], kv[4];
#pragma unroll
            for (int ri = 0; ri < 4; ri++)
                qv[ri] = *(const float4*)(Qs + (tr*4 + ri) * SP + k0);
#pragma unroll
            for (int ci = 0; ci < 4; ci++)
                kv[ci] = *(const float4*)(Ks + (tc*4 + ci) * SP + k0);
#pragma unroll
            for (int ri = 0; ri < 4; ri++)
#pragma unroll
                for (int ci = 0; ci < 4; ci++) {
                    sv[ri][ci] = fmaf(qv[ri].x, kv[ci].x, sv[ri][ci]);
                    sv[ri][ci] = fmaf(qv[ri].y, kv[ci].y, sv[ri][ci]);
                    sv[ri][ci] = fmaf(qv[ri].z, kv[ci].z, sv[ri][ci]);
                    sv[ri][ci] = fmaf(qv[ri].w, kv[ci].w, sv[ri][ci]);
                }
        }

        const int rg0 = qt * BR + tr * 4;
        const int cg0 = jb * BC + tc * 4;
#pragma unroll
        for (int ri = 0; ri < 4; ri++) {
#pragma unroll
            for (int ci = 0; ci < 4; ci++) {
                float x = sv[ri][ci] * scale;
                if (cg0 + ci > rg0 + ri) x = -1e30f;
                sv[ri][ci] = x;
            }
            float rm = fmaxf(fmaxf(sv[ri][0], sv[ri][1]), fmaxf(sv[ri][2], sv[ri][3]));
#pragma unroll
            for (int o = 8; o >= 1; o >>= 1)
                rm = fmaxf(rm, __shfl_xor_sync(0xffffffffu, rm, o));
            float mnew = fmaxf(m_i[ri], rm);
            float alph = expf(m_i[ri] - mnew);
            m_i[ri] = mnew;
            float rs = 0.f;
#pragma unroll
            for (int ci = 0; ci < 4; ci++) {
                float p = expf(sv[ri][ci] - mnew);
                sv[ri][ci] = p;
                rs += p;
            }
#pragma unroll
            for (int o = 8; o >= 1; o >>= 1)
                rs += __shfl_xor_sync(0xffffffffu, rs, o);
            l_i[ri] = l_i[ri] * alph + rs;
#pragma unroll
            for (int j = 0; j < 8; j++) acc[ri][j] *= alph;
#pragma unroll
            for (int ci = 0; ci < 4; ci++)
                Ps[(tr*4 + ri) * PSP + tc*4 + ci] = sv[ri][ci];
        }
        __syncthreads();

#pragma unroll 4
        for (int c = 0; c < BC; c++) {
            float4 v0 = *(const float4*)(Vs + c * SP + tc * 8);
            float4 v1 = *(const float4*)(Vs + c * SP + tc * 8 + 4);
#pragma unroll
            for (int ri = 0; ri < 4; ri++) {
                float p = Ps[(tr*4 + ri) * PSP + c];
                acc[ri][0] = fmaf(p, v0.x, acc[ri][0]);
                acc[ri][1] = fmaf(p, v0.y, acc[ri][1]);
                acc[ri][2] = fmaf(p, v0.z, acc[ri][2]);
                acc[ri][3] = fmaf(p, v0.w, acc[ri][3]);
                acc[ri][4] = fmaf(p, v1.x, acc[ri][4]);
                acc[ri][5] = fmaf(p, v1.y, acc[ri][5]);
                acc[ri][6] = fmaf(p, v1.z, acc[ri][6]);
                acc[ri][7] = fmaf(p, v1.w, acc[ri][7]);
            }
        }
    }

#pragma unroll
    for (int ri = 0; ri < 4; ri++) {
        float inv = 1.f / l_i[ri];
        int srow = qt * BR + tr * 4 + ri;
        float* o = gout + ((size_t)b * S_ + srow) * D_ + (h << 7) + tc * 8;
        float4 r0, r1;
        r0.x = acc[ri][0]*inv; r0.y = acc[ri][1]*inv; r0.z = acc[ri][2]*inv; r0.w = acc[ri][3]*inv;
        r1.x = acc[ri][4]*inv; r1.y = acc[ri][5]*inv; r1.z = acc[ri][6]*inv; r1.w = acc[ri][7]*inv;
        *(float4*)(o)     = r0;
        *(float4*)(o + 4) = r1;
    }
}

// ---------------- launch ----------------
extern "C" void kernel_launch(void* const* d_in, const int* in_sizes, int n_in,
                              void* d_out, int out_size)
{
    const float* query = (const float*)d_in[0];
    const float* key   = (const float*)d_in[1];
    const float* value = (const float*)d_in[2];
    const float* wq = (const float*)d_in[4];
    const float* bq = (const float*)d_in[5];
    const float* wk = (const float*)d_in[6];
    const float* bk = (const float*)d_in[7];
    const float* wv = (const float*)d_in[8];
    const float* bv = (const float*)d_in[9];
    const float* wo = (const float*)d_in[10];
    const float* bo = (const float*)d_in[11];
    float* out = (float*)d_out;

    float *q_s, *k_s, *v_s, *attn_s;
    __nv_bfloat16 *acat, *wcat;
    cudaGetSymbolAddress((void**)&q_s, g_q);
    cudaGetSymbolAddress((void**)&k_s, g_k);
    cudaGetSymbolAddress((void**)&v_s, g_v);
    cudaGetSymbolAddress((void**)&attn_s, g_attn);
    cudaGetSymbolAddress((void**)&acat, g_acat);
    cudaGetSymbolAddress((void**)&wcat, g_wcat);

    cudaFuncSetAttribute(attn_kernel, cudaFuncAttributeMaxDynamicSharedMemorySize, ATTN_SMEM);
    cudaFuncSetAttribute(gemm_mma, cudaFuncAttributeMaxDynamicSharedMemorySize, GEMM_SMEM);

    const int wgrid = (D_ * D_ / 4 + 255) / 256;
    const int agrid = (M_ * D_ / 4 + 255) / 256;
    dim3 ggrid(D_ / 128, M_ / 128);                // (16, 32)

    // Q projection
    split_kernel<<<agrid, 256>>>(query, acat, M_ * D_, 1);
    split_kernel<<<wgrid, 256>>>(wq, wcat, D_ * D_, 0);
    gemm_mma<<<ggrid, 256, GEMM_SMEM>>>(acat, wcat, bq, q_s, 1);
    // K projection
    split_kernel<<<agrid, 256>>>(key, acat, M_ * D_, 1);
    split_kernel<<<wgrid, 256>>>(wk, wcat, D_ * D_, 0);
    gemm_mma<<<ggrid, 256, GEMM_SMEM>>>(acat, wcat, bk, k_s, 1);
    // V projection
    split_kernel<<<agrid, 256>>>(value, acat, M_ * D_, 1);
    split_kernel<<<wgrid, 256>>>(wv, wcat, D_ * D_, 0);
    gemm_mma<<<ggrid, 256, GEMM_SMEM>>>(acat, wcat, bv, v_s, 1);

    rope_table<<<(S_ * 64) / 256, 256>>>();
    rope_apply<<<(B_ * H_ * S_ * 64) / 256, 256>>>();

    attn_kernel<<<dim3(S_ / BR, B_ * H_), 256, ATTN_SMEM>>>(q_s, k_s, v_s, attn_s);

    // Output projection
    split_kernel<<<agrid, 256>>>(attn_s, acat, M_ * D_, 1);
    split_kernel<<<wgrid, 256>>>(wo, wcat, D_ * D_, 0);
    gemm_mma<<<ggrid, 256, GEMM_SMEM>>>(acat, wcat, bo, out, 0);
}

// round 6
// speedup vs baseline: 3.0242x; 1.8974x over previous
#include <cuda_runtime.h>
#include <cuda_bf16.h>
#include <math.h>
#include <stdint.h>

#define B_  2
#define S_  2048
#define D_  2048
#define H_  16
#define DK_ 128
#define M_  (B_*S_)   // 4096
#define BH_ (B_*H_)   // 32
#define K3_ 6144      // 3*D_ (bf16x3 split concat)
#define NCH 96        // K3_/64 chunks

// ---------------- scratch (device globals; no allocs allowed) ----------------
__device__ __nv_bfloat16 g_acat[M_*K3_];   // 48MB  activation cat [hi|hi|lo]
__device__ __nv_bfloat16 g_wcat[D_*K3_];   // 24MB  weight cat     [hi|lo|hi]
__device__ float g_q[BH_*S_*DK_];
__device__ float g_k[BH_*S_*DK_];
__device__ float g_v[BH_*S_*DK_];
__device__ float g_attn[B_*S_*D_];
__device__ float g_cos[S_*64];
__device__ float g_sin[S_*64];
// attention bf16x3 operands
__device__ __nv_bfloat16 g_qh[BH_*S_*DK_], g_ql[BH_*S_*DK_];
__device__ __nv_bfloat16 g_kh[BH_*S_*DK_], g_kl[BH_*S_*DK_];
__device__ __nv_bfloat16 g_vth[BH_*DK_*S_], g_vtl[BH_*DK_*S_];  // [bh][d][s]

__device__ __forceinline__ uint32_t smem_u32(const void* p) {
    uint32_t a;
    asm("{ .reg .u64 t; cvta.to.shared.u64 t, %1; cvt.u32.u64 %0, t; }" : "=r"(a) : "l"(p));
    return a;
}

#define LDSM4(r0,r1,r2,r3, addr) \
    asm volatile("ldmatrix.sync.aligned.m8n8.x4.shared.b16 {%0,%1,%2,%3}, [%4];" \
        : "=r"(r0), "=r"(r1), "=r"(r2), "=r"(r3) : "r"(addr))

#define MMA16816(d, a, b0v, b1v) \
    asm volatile("mma.sync.aligned.m16n8k16.row.col.f32.bf16.bf16.f32 " \
        "{%0,%1,%2,%3}, {%4,%5,%6,%7}, {%8,%9}, {%0,%1,%2,%3};" \
        : "+f"((d)[0]), "+f"((d)[1]), "+f"((d)[2]), "+f"((d)[3]) \
        : "r"((a)[0]), "r"((a)[1]), "r"((a)[2]), "r"((a)[3]), "r"(b0v), "r"(b1v))

#define CPA16(dst, src) \
    asm volatile("cp.async.cg.shared.global [%0], [%1], 16;" :: "r"(dst), "l"(src))

// ---------------- bf16 split: out rows of 6144 = [hi | s1 | s2] ----------------
__global__ __launch_bounds__(256) void split_kernel(
    const float* __restrict__ x, __nv_bfloat16* __restrict__ out, int nelem, int act)
{
    int i4 = (blockIdx.x * 256 + threadIdx.x) * 4;
    if (i4 >= nelem) return;
    int r = i4 >> 11, c = i4 & 2047;
    float4 v = *(const float4*)(x + i4);
    __nv_bfloat16 h0 = __float2bfloat16(v.x), h1 = __float2bfloat16(v.y);
    __nv_bfloat16 h2 = __float2bfloat16(v.z), h3 = __float2bfloat16(v.w);
    __nv_bfloat16 l0 = __float2bfloat16(v.x - __bfloat162float(h0));
    __nv_bfloat16 l1 = __float2bfloat16(v.y - __bfloat162float(h1));
    __nv_bfloat16 l2 = __float2bfloat16(v.z - __bfloat162float(h2));
    __nv_bfloat16 l3 = __float2bfloat16(v.w - __bfloat162float(h3));
    __nv_bfloat162 H01, H23, L01, L23;
    H01.x = h0; H01.y = h1; H23.x = h2; H23.y = h3;
    L01.x = l0; L01.y = l1; L23.x = l2; L23.y = l3;
    __nv_bfloat16* row = out + (size_t)r * K3_ + c;
    *(__nv_bfloat162*)(row)     = H01;
    *(__nv_bfloat162*)(row + 2) = H23;
    if (act) {
        *(__nv_bfloat162*)(row + 2048)     = H01;
        *(__nv_bfloat162*)(row + 2048 + 2) = H23;
        *(__nv_bfloat162*)(row + 4096)     = L01;
        *(__nv_bfloat162*)(row + 4096 + 2) = L23;
    } else {
        *(__nv_bfloat162*)(row + 2048)     = L01;
        *(__nv_bfloat162*)(row + 2048 + 2) = L23;
        *(__nv_bfloat162*)(row + 4096)     = H01;
        *(__nv_bfloat162*)(row + 4096 + 2) = H23;
    }
}

// ---------------- mma.sync GEMM (unchanged, passing) ----------------
#define LDA 72
#define TILE_E (128*LDA)
#define NSTAGE 3
#define GEMM_SMEM (NSTAGE*2*TILE_E*2)

__global__ __launch_bounds__(256, 2) void gemm_mma(
    const __nv_bfloat16* __restrict__ A, const __nv_bfloat16* __restrict__ Wt,
    const float* __restrict__ bias, float* __restrict__ C, int headed)
{
    extern __shared__ __nv_bfloat16 sm[];
    __nv_bfloat16* AsB = sm;
    __nv_bfloat16* BsB = sm + NSTAGE * TILE_E;
    const int tid = threadIdx.x;
    const int lane = tid & 31, w = tid >> 5;
    const int wm = (w >> 2) << 6;
    const int wn = (w & 3) << 5;
    const int m0 = blockIdx.y << 7, n0 = blockIdx.x << 7;

    const __nv_bfloat16* Ag = A  + (size_t)m0 * K3_;
    const __nv_bfloat16* Wg = Wt + (size_t)n0 * K3_;

    float acc[4][4][4];
#pragma unroll
    for (int mi = 0; mi < 4; mi++)
#pragma unroll
        for (int ni = 0; ni < 4; ni++)
#pragma unroll
            for (int j = 0; j < 4; j++) acc[mi][ni][j] = 0.f;

    const int lrow = tid >> 3, lc8 = (tid & 7) << 3;
#define LOAD_CHUNK(stage, chunk) do {                                            \
    __nv_bfloat16* as = AsB + (stage) * TILE_E;                                  \
    __nv_bfloat16* bs = BsB + (stage) * TILE_E;                                  \
    const __nv_bfloat16* Ac = Ag + (size_t)(chunk) * 64;                         \
    const __nv_bfloat16* Wc = Wg + (size_t)(chunk) * 64;                         \
    _Pragma("unroll")                                                            \
    for (int i = 0; i < 4; i++) {                                                \
        int row = lrow + i * 32;                                                 \
        uint32_t sa = smem_u32(as + row * LDA + lc8);                            \
        uint32_t sbp = smem_u32(bs + row * LDA + lc8);                           \
        CPA16(sa, Ac + (size_t)row * K3_ + lc8);                                 \
        CPA16(sbp, Wc + (size_t)row * K3_ + lc8);                                \
    }                                                                            \
    asm volatile("cp.async.commit_group;" ::: "memory");                         \
} while (0)

    LOAD_CHUNK(0, 0);
    LOAD_CHUNK(1, 1);

    for (int c = 0; c < NCH; c++) {
        const int s = c % NSTAGE;
        if (c + 1 < NCH) {
            asm volatile("cp.async.wait_group 1;" ::: "memory");
        } else {
            asm volatile("cp.async.wait_group 0;" ::: "memory");
        }
        __syncthreads();

        if (c + 2 < NCH) LOAD_CHUNK((c + 2) % NSTAGE, c + 2);

        const __nv_bfloat16* as = AsB + s * TILE_E;
        const __nv_bfloat16* bs = BsB + s * TILE_E;
#pragma unroll
        for (int ks = 0; ks < 4; ks++) {
            const int kc = ks << 4;
            uint32_t a[4][4];
#pragma unroll
            for (int mi = 0; mi < 4; mi++) {
                int r = wm + (mi << 4) + (lane & 15);
                int cc = kc + ((lane >> 4) << 3);
                uint32_t ad = smem_u32(as + r * LDA + cc);
                LDSM4(a[mi][0], a[mi][1], a[mi][2], a[mi][3], ad);
            }
            uint32_t b[4][2];
#pragma unroll
            for (int nb = 0; nb < 2; nb++) {
                int r = wn + (nb << 4) + (lane & 7) + (((lane >> 4) & 1) << 3);
                int cc = kc + (((lane >> 3) & 1) << 3);
                uint32_t ad = smem_u32(bs + r * LDA + cc);
                LDSM4(b[nb*2][0], b[nb*2][1], b[nb*2+1][0], b[nb*2+1][1], ad);
            }
#pragma unroll
            for (int mi = 0; mi < 4; mi++)
#pragma unroll
                for (int ni = 0; ni < 4; ni++)
                    MMA16816(acc[mi][ni], a[mi], b[ni][0], b[ni][1]);
        }
    }

#pragma unroll
    for (int mi = 0; mi < 4; mi++) {
#pragma unroll
        for (int half = 0; half < 2; half++) {
            int m = m0 + wm + (mi << 4) + (lane >> 2) + (half << 3);
            float* dst;
#pragma unroll
            for (int ni = 0; ni < 4; ni++) {
                int n = n0 + wn + (ni << 3) + ((lane & 3) << 1);
                float2 o;
                o.x = acc[mi][ni][half*2+0] + bias[n];
                o.y = acc[mi][ni][half*2+1] + bias[n+1];
                if (headed) {
                    int b = m >> 11, sidx = m & (S_ - 1), h = n >> 7, dk = n & (DK_ - 1);
                    dst = C + ((((size_t)b * H_ + h) * S_ + sidx) << 7) + dk;
                } else {
                    dst = C + (size_t)m * D_ + n;
                }
                *(float2*)dst = o;
            }
        }
    }
}

// ---------------- RoPE table ----------------
__global__ __launch_bounds__(256) void rope_table()
{
    int idx = blockIdx.x * blockDim.x + threadIdx.x;
    if (idx >= S_ * 64) return;
    int i = idx & 63;
    int s = idx >> 6;
    float inv = powf(10000.f, -(float)(2 * i) / 128.f);
    float ph  = (float)s * inv;
    g_cos[idx] = cosf(ph);
    g_sin[idx] = sinf(ph);
}

// ---------------- RoPE + hi/lo split for q,k ----------------
__global__ __launch_bounds__(256) void rope_split()
{
    int idx = blockIdx.x * blockDim.x + threadIdx.x;  // BH*S*64
    int i  = idx & 63;
    int s  = (idx >> 6) & (S_ - 1);
    int bh = idx >> 17;
    float c  = g_cos[(s << 6) + i];
    float sn = g_sin[(s << 6) + i];
    size_t base = ((size_t)bh * S_ + s) << 7;

    float q1 = g_q[base + i], q2 = g_q[base + 64 + i];
    float r1 = q1 * c - q2 * sn;
    float r2 = q2 * c + q1 * sn;
    __nv_bfloat16 h1 = __float2bfloat16(r1), h2 = __float2bfloat16(r2);
    g_qh[base + i]      = h1;
    g_qh[base + 64 + i] = h2;
    g_ql[base + i]      = __float2bfloat16(r1 - __bfloat162float(h1));
    g_ql[base + 64 + i] = __float2bfloat16(r2 - __bfloat162float(h2));

    float k1 = g_k[base + i], k2 = g_k[base + 64 + i];
    float t1 = k1 * c - k2 * sn;
    float t2 = k2 * c + k1 * sn;
    __nv_bfloat16 g1 = __float2bfloat16(t1), g2 = __float2bfloat16(t2);
    g_kh[base + i]      = g1;
    g_kh[base + 64 + i] = g2;
    g_kl[base + i]      = __float2bfloat16(t1 - __bfloat162float(g1));
    g_kl[base + 64 + i] = __float2bfloat16(t2 - __bfloat162float(g2));
}

// ---------------- V transpose + split: [bh][s][d] -> [bh][d][s] hi/lo ----------------
__global__ __launch_bounds__(256) void v_split()
{
    __shared__ float smt[32][33];
    int bh = blockIdx.z;
    int s0 = blockIdx.x << 5, d0 = blockIdx.y << 5;
    int tx = threadIdx.x, ty = threadIdx.y;   // (32, 8)
#pragma unroll
    for (int i = 0; i < 4; i++) {
        int r = ty + (i << 3);
        smt[r][tx] = g_v[(((size_t)bh * S_ + s0 + r) << 7) + d0 + tx];
    }
    __syncthreads();
#pragma unroll
    for (int i = 0; i < 4; i++) {
        int dd = ty + (i << 3);
        float v = smt[tx][dd];
        __nv_bfloat16 h = __float2bfloat16(v);
        size_t o = ((size_t)bh * DK_ + d0 + dd) * S_ + s0 + tx;
        g_vth[o] = h;
        g_vtl[o] = __float2bfloat16(v - __bfloat162float(h));
    }
}

// ---------------- tensor-core causal flash attention (bf16x3) ----------------
// BR=128 q rows/CTA, 8 warps x 16 rows, BC=64 keys/iter, 2-stage cp.async KV.
#define QLD 136            // padded row stride for Q/K (128 cols)
#define VLD 72             // padded row stride for Vt (64 cols)
#define oQH 0
#define oQL 17408
#define oKV 34816
#define stKV 35840         // per stage: KH 8704 + KL 8704 + VH 9216 + VL 9216
#define ATTN2_SMEM ((oKV + 2*stKV)*2)   // 212992 B

__global__ __launch_bounds__(256, 1) void attn_mma(
    const __nv_bfloat16* __restrict__ gqh, const __nv_bfloat16* __restrict__ gql,
    const __nv_bfloat16* __restrict__ gkh, const __nv_bfloat16* __restrict__ gkl,
    const __nv_bfloat16* __restrict__ gvh, const __nv_bfloat16* __restrict__ gvl,
    float* __restrict__ gout)
{
    extern __shared__ __nv_bfloat16 smb[];
    const uint32_t usm = smem_u32(smb);
    const int tid = threadIdx.x;
    const int lane = tid & 31, w = tid >> 5;
    const int wrow = w << 4;                 // warp q-row offset (16 rows)
    const int qt = blockIdx.x;               // q tile (128 rows)
    const int bh = blockIdx.y;
    const int b  = bh >> 4, h = bh & 15;
    const int nblk = 2 * qt + 2;
    const float SCL2 = 0.12751743f;          // 1/sqrt(128) * log2(e)

    const size_t qbase = ((size_t)bh * S_ + (size_t)qt * 128) << 7;

    // ---- initial loads: Q (hi/lo) + KV stage 0 -> group0, KV stage1 -> group1
    {
#pragma unroll
        for (int i = 0; i < 8; i++) {
            int ch = tid + (i << 8);         // 0..2047
            int r = ch >> 4, c8 = (ch & 15) << 3;
            CPA16(usm + (uint32_t)(oQH + r * QLD + c8) * 2, gqh + qbase + ((size_t)r << 7) + c8);
            CPA16(usm + (uint32_t)(oQL + r * QLD + c8) * 2, gql + qbase + ((size_t)r << 7) + c8);
        }
    }
#define LOAD_KV(stage, jb) do {                                                      \
    uint32_t kvb = oKV + (stage) * stKV;                                             \
    size_t kbase = ((size_t)bh * S_ + (size_t)(jb) * 64) << 7;                       \
    _Pragma("unroll")                                                                \
    for (int i = 0; i < 4; i++) {                                                    \
        int ch = tid + (i << 8);            /* 0..1023 */                            \
        int r = ch >> 4, c8 = (ch & 15) << 3;                                        \
        CPA16(usm + (kvb + r * QLD + c8) * 2,        gkh + kbase + ((size_t)r << 7) + c8); \
        CPA16(usm + (kvb + 8704 + r * QLD + c8) * 2, gkl + kbase + ((size_t)r << 7) + c8); \
    }                                                                                \
    size_t vbase = ((size_t)bh * DK_) * S_ + (size_t)(jb) * 64;                      \
    _Pragma("unroll")                                                                \
    for (int i = 0; i < 4; i++) {                                                    \
        int ch = tid + (i << 8);                                                     \
        int r = ch >> 3, c8 = (ch & 7) << 3;                                         \
        CPA16(usm + (kvb + 17408 + r * VLD + c8) * 2, gvh + vbase + (size_t)r * S_ + c8); \
        CPA16(usm + (kvb + 26624 + r * VLD + c8) * 2, gvl + vbase + (size_t)r * S_ + c8); \
    }                                                                                \
    asm volatile("cp.async.commit_group;" ::: "memory");                             \
} while (0)

    LOAD_KV(0, 0);     // group 0 (includes Q)
    LOAD_KV(1, 1);     // group 1

    float oa[16][4];
#pragma unroll
    for (int nt = 0; nt < 16; nt++)
#pragma unroll
        for (int j = 0; j < 4; j++) oa[nt][j] = 0.f;
    float m0r = -1e30f, m1r = -1e30f, l0r = 0.f, l1r = 0.f;

    const int grow0 = qt * 128 + wrow + (lane >> 2);
    const int grow1 = grow0 + 8;

    for (int jb = 0; jb < nblk; jb++) {
        const int st = jb & 1;
        if (jb + 1 < nblk) {
            asm volatile("cp.async.wait_group 1;" ::: "memory");
        } else {
            asm volatile("cp.async.wait_group 0;" ::: "memory");
        }
        __syncthreads();

        const uint32_t kvb = oKV + st * stKV;

        // ---- S = Q K^T (3-term bf16x3), per-warp 16x64 fp32 frags
        float sa[8][4];
#pragma unroll
        for (int nt = 0; nt < 8; nt++)
#pragma unroll
            for (int j = 0; j < 4; j++) sa[nt][j] = 0.f;

#pragma unroll
        for (int kt = 0; kt < 8; kt++) {
            const int kc = kt << 4;
            uint32_t ah[4], al[4];
            {
                int r = wrow + (lane & 15);
                int cc = kc + ((lane >> 4) << 3);
                LDSM4(ah[0], ah[1], ah[2], ah[3], usm + (uint32_t)(oQH + r * QLD + cc) * 2);
                LDSM4(al[0], al[1], al[2], al[3], usm + (uint32_t)(oQL + r * QLD + cc) * 2);
            }
#pragma unroll
            for (int ntp = 0; ntp < 4; ntp++) {
                int r = (ntp << 4) + (lane & 7) + (((lane >> 4) & 1) << 3);
                int cc = kc + (((lane >> 3) & 1) << 3);
                uint32_t bhh[4], bll[4];
                LDSM4(bhh[0], bhh[1], bhh[2], bhh[3], usm + (kvb + r * QLD + cc) * 2);
                LDSM4(bll[0], bll[1], bll[2], bll[3], usm + (kvb + 8704 + r * QLD + cc) * 2);
#pragma unroll
                for (int t = 0; t < 2; t++) {
                    int nt = (ntp << 1) + t;
                    MMA16816(sa[nt], ah, bhh[2*t], bhh[2*t+1]);
                    MMA16816(sa[nt], ah, bll[2*t], bll[2*t+1]);
                    MMA16816(sa[nt], al, bhh[2*t], bhh[2*t+1]);
                }
            }
        }

        // ---- scale (+mask) in log2 domain
        const bool needmask = (jb >= 2 * qt);
#pragma unroll
        for (int nt = 0; nt < 8; nt++) {
            int cb = jb * 64 + (nt << 3) + ((lane & 3) << 1);
#pragma unroll
            for (int j = 0; j < 4; j++) {
                float x = sa[nt][j] * SCL2;
                if (needmask) {
                    int col = cb + (j & 1);
                    int row = (j < 2) ? grow0 : grow1;
                    if (col > row) x = -1e30f;
                }
                sa[nt][j] = x;
            }
        }

        // ---- online softmax (rows warp-local; reduce over lane%4 group)
        float rm0 = -1e30f, rm1 = -1e30f;
#pragma unroll
        for (int nt = 0; nt < 8; nt++) {
            rm0 = fmaxf(rm0, fmaxf(sa[nt][0], sa[nt][1]));
            rm1 = fmaxf(rm1, fmaxf(sa[nt][2], sa[nt][3]));
        }
        rm0 = fmaxf(rm0, __shfl_xor_sync(0xffffffffu, rm0, 1));
        rm0 = fmaxf(rm0, __shfl_xor_sync(0xffffffffu, rm0, 2));
        rm1 = fmaxf(rm1, __shfl_xor_sync(0xffffffffu, rm1, 1));
        rm1 = fmaxf(rm1, __shfl_xor_sync(0xffffffffu, rm1, 2));
        float mn0 = fmaxf(m0r, rm0), mn1 = fmaxf(m1r, rm1);
        float al0 = exp2f(m0r - mn0), al1 = exp2f(m1r - mn1);
        m0r = mn0; m1r = mn1;

        float rs0 = 0.f, rs1 = 0.f;
#pragma unroll
        for (int nt = 0; nt < 8; nt++) {
            float p0 = exp2f(sa[nt][0] - mn0);
            float p1 = exp2f(sa[nt][1] - mn0);
            float p2 = exp2f(sa[nt][2] - mn1);
            float p3 = exp2f(sa[nt][3] - mn1);
            sa[nt][0] = p0; sa[nt][1] = p1; sa[nt][2] = p2; sa[nt][3] = p3;
            rs0 += p0 + p1; rs1 += p2 + p3;
        }
        rs0 += __shfl_xor_sync(0xffffffffu, rs0, 1);
        rs0 += __shfl_xor_sync(0xffffffffu, rs0, 2);
        rs1 += __shfl_xor_sync(0xffffffffu, rs1, 1);
        rs1 += __shfl_xor_sync(0xffffffffu, rs1, 2);
        l0r = l0r * al0 + rs0;
        l1r = l1r * al1 + rs1;

#pragma unroll
        for (int nt = 0; nt < 16; nt++) {
            oa[nt][0] *= al0; oa[nt][1] *= al0;
            oa[nt][2] *= al1; oa[nt][3] *= al1;
        }

        // ---- O += P V  (P hi/lo built in registers; 3 terms vs Vt hi/lo)
#pragma unroll
        for (int kt2 = 0; kt2 < 4; kt2++) {
            const int t0 = kt2 << 1, t1 = t0 + 1;
            uint32_t pah[4], pal[4];
            {
                __nv_bfloat162 hh, ll;
                float p0, p1, r0, r1;
                p0 = sa[t0][0]; p1 = sa[t0][1];
                hh = __floats2bfloat162_rn(p0, p1);
                r0 = p0 - __bfloat162float(hh.x); r1 = p1 - __bfloat162float(hh.y);
                ll = __floats2bfloat162_rn(r0, r1);
                pah[0] = *(uint32_t*)&hh; pal[0] = *(uint32_t*)&ll;
                p0 = sa[t0][2]; p1 = sa[t0][3];
                hh = __floats2bfloat162_rn(p0, p1);
                r0 = p0 - __bfloat162float(hh.x); r1 = p1 - __bfloat162float(hh.y);
                ll = __floats2bfloat162_rn(r0, r1);
                pah[1] = *(uint32_t*)&hh; pal[1] = *(uint32_t*)&ll;
                p0 = sa[t1][0]; p1 = sa[t1][1];
                hh = __floats2bfloat162_rn(p0, p1);
                r0 = p0 - __bfloat162float(hh.x); r1 = p1 - __bfloat162float(hh.y);
                ll = __floats2bfloat162_rn(r0, r1);
                pah[2] = *(uint32_t*)&hh; pal[2] = *(uint32_t*)&ll;
                p0 = sa[t1][2]; p1 = sa[t1][3];
                hh = __floats2bfloat162_rn(p0, p1);
                r0 = p0 - __bfloat162float(hh.x); r1 = p1 - __bfloat162float(hh.y);
                ll = __floats2bfloat162_rn(r0, r1);
                pah[3] = *(uint32_t*)&hh; pal[3] = *(uint32_t*)&ll;
            }
            const int cv = (kt2 << 4) + (((lane >> 3) & 1) << 3);
#pragma unroll
            for (int ntp = 0; ntp < 8; ntp++) {
                int r = (ntp << 4) + (lane & 7) + (((lane >> 4) & 1) << 3);
                uint32_t vhh[4], vll[4];
                LDSM4(vhh[0], vhh[1], vhh[2], vhh[3], usm + (kvb + 17408 + r * VLD + cv) * 2);
                LDSM4(vll[0], vll[1], vll[2], vll[3], usm + (kvb + 26624 + r * VLD + cv) * 2);
#pragma unroll
                for (int t = 0; t < 2; t++) {
                    int nt = (ntp << 1) + t;
                    MMA16816(oa[nt], pah, vhh[2*t], vhh[2*t+1]);
                    MMA16816(oa[nt], pah, vll[2*t], vll[2*t+1]);
                    MMA16816(oa[nt], pal, vhh[2*t], vhh[2*t+1]);
                }
            }
        }

        __syncthreads();   // all warps done reading stage st
        if (jb + 2 < nblk) LOAD_KV(st, jb + 2);
    }

    // ---- epilogue: O /= l, write [B,S,D] at col h*128 + d
    float inv0 = 1.f / l0r, inv1 = 1.f / l1r;
    int srow0 = qt * 128 + wrow + (lane >> 2);
    float* o0 = gout + ((size_t)b * S_ + srow0) * D_ + (h << 7);
    float* o1 = o0 + 8 * D_;
#pragma unroll
    for (int nt = 0; nt < 16; nt++) {
        int cb = (nt << 3) + ((lane & 3) << 1);
        float2 v0, v1;
        v0.x = oa[nt][0] * inv0; v0.y = oa[nt][1] * inv0;
        v1.x = oa[nt][2] * inv1; v1.y = oa[nt][3] * inv1;
        *(float2*)(o0 + cb) = v0;
        *(float2*)(o1 + cb) = v1;
    }
}

// ---------------- launch ----------------
extern "C" void kernel_launch(void* const* d_in, const int* in_sizes, int n_in,
                              void* d_out, int out_size)
{
    const float* query = (const float*)d_in[0];
    const float* key   = (const float*)d_in[1];
    const float* value = (const float*)d_in[2];
    const float* wq = (const float*)d_in[4];
    const float* bq = (const float*)d_in[5];
    const float* wk = (const float*)d_in[6];
    const float* bk = (const float*)d_in[7];
    const float* wv = (const float*)d_in[8];
    const float* bv = (const float*)d_in[9];
    const float* wo = (const float*)d_in[10];
    const float* bo = (const float*)d_in[11];
    float* out = (float*)d_out;

    float *q_s, *k_s, *v_s, *attn_s;
    __nv_bfloat16 *acat, *wcat, *qh, *ql, *kh, *kl, *vth, *vtl;
    cudaGetSymbolAddress((void**)&q_s, g_q);
    cudaGetSymbolAddress((void**)&k_s, g_k);
    cudaGetSymbolAddress((void**)&v_s, g_v);
    cudaGetSymbolAddress((void**)&attn_s, g_attn);
    cudaGetSymbolAddress((void**)&acat, g_acat);
    cudaGetSymbolAddress((void**)&wcat, g_wcat);
    cudaGetSymbolAddress((void**)&qh, g_qh);
    cudaGetSymbolAddress((void**)&ql, g_ql);
    cudaGetSymbolAddress((void**)&kh, g_kh);
    cudaGetSymbolAddress((void**)&kl, g_kl);
    cudaGetSymbolAddress((void**)&vth, g_vth);
    cudaGetSymbolAddress((void**)&vtl, g_vtl);

    cudaFuncSetAttribute(gemm_mma, cudaFuncAttributeMaxDynamicSharedMemorySize, GEMM_SMEM);
    cudaFuncSetAttribute(attn_mma, cudaFuncAttributeMaxDynamicSharedMemorySize, ATTN2_SMEM);

    const int wgrid = (D_ * D_ / 4 + 255) / 256;
    const int agrid = (M_ * D_ / 4 + 255) / 256;
    dim3 ggrid(D_ / 128, M_ / 128);

    // Q projection
    split_kernel<<<agrid, 256>>>(query, acat, M_ * D_, 1);
    split_kernel<<<wgrid, 256>>>(wq, wcat, D_ * D_, 0);
    gemm_mma<<<ggrid, 256, GEMM_SMEM>>>(acat, wcat, bq, q_s, 1);
    // K projection
    split_kernel<<<agrid, 256>>>(key, acat, M_ * D_, 1);
    split_kernel<<<wgrid, 256>>>(wk, wcat, D_ * D_, 0);
    gemm_mma<<<ggrid, 256, GEMM_SMEM>>>(acat, wcat, bk, k_s, 1);
    // V projection
    split_kernel<<<agrid, 256>>>(value, acat, M_ * D_, 1);
    split_kernel<<<wgrid, 256>>>(wv, wcat, D_ * D_, 0);
    gemm_mma<<<ggrid, 256, GEMM_SMEM>>>(acat, wcat, bv, v_s, 1);

    rope_table<<<(S_ * 64) / 256, 256>>>();
    rope_split<<<(BH_ * S_ * 64) / 256, 256>>>();
    v_split<<<dim3(S_ / 32, DK_ / 32, BH_), dim3(32, 8)>>>();

    attn_mma<<<dim3(S_ / 128, BH_), 256, ATTN2_SMEM>>>(qh, ql, kh, kl, vth, vtl, attn_s);

    // Output projection
    split_kernel<<<agrid, 256>>>(attn_s, acat, M_ * D_, 1);
    split_kernel<<<wgrid, 256>>>(wo, wcat, D_ * D_, 0);
    gemm_mma<<<ggrid, 256, GEMM_SMEM>>>(acat, wcat, bo, out, 0);
}

// round 7
// speedup vs baseline: 3.1185x; 1.0312x over previous
#include <cuda_runtime.h>
#include <cuda_bf16.h>
#include <math.h>
#include <stdint.h>

#define B_  2
#define S_  2048
#define D_  2048
#define H_  16
#define DK_ 128
#define M_  (B_*S_)   // 4096
#define BH_ (B_*H_)   // 32
#define K2_ 4096      // [hi | lo] dedup layout

// ---------------- scratch (device globals; no allocs allowed) ----------------
__device__ __nv_bfloat16 g_acat[M_*K2_];   // 32MB  activation [hi|lo]
__device__ __nv_bfloat16 g_wcat[D_*K2_];   // 16MB  weight     [hi|lo]
__device__ float g_q[BH_*S_*DK_];
__device__ float g_k[BH_*S_*DK_];
__device__ float g_v[BH_*S_*DK_];
__device__ float g_cos[S_*64];
__device__ float g_sin[S_*64];
__device__ __nv_bfloat16 g_qh[BH_*S_*DK_], g_ql[BH_*S_*DK_];
__device__ __nv_bfloat16 g_kh[BH_*S_*DK_], g_kl[BH_*S_*DK_];
__device__ __nv_bfloat16 g_vth[BH_*DK_*S_], g_vtl[BH_*DK_*S_];  // [bh][d][s]

__device__ __forceinline__ uint32_t smem_u32(const void* p) {
    uint32_t a;
    asm("{ .reg .u64 t; cvta.to.shared.u64 t, %1; cvt.u32.u64 %0, t; }" : "=r"(a) : "l"(p));
    return a;
}

#define LDSM4(r0,r1,r2,r3, addr) \
    asm volatile("ldmatrix.sync.aligned.m8n8.x4.shared.b16 {%0,%1,%2,%3}, [%4];" \
        : "=r"(r0), "=r"(r1), "=r"(r2), "=r"(r3) : "r"(addr))

#define MMA16816(d, a, b0v, b1v) \
    asm volatile("mma.sync.aligned.m16n8k16.row.col.f32.bf16.bf16.f32 " \
        "{%0,%1,%2,%3}, {%4,%5,%6,%7}, {%8,%9}, {%0,%1,%2,%3};" \
        : "+f"((d)[0]), "+f"((d)[1]), "+f"((d)[2]), "+f"((d)[3]) \
        : "r"((a)[0]), "r"((a)[1]), "r"((a)[2]), "r"((a)[3]), "r"(b0v), "r"(b1v))

#define CPA16(dst, src) \
    asm volatile("cp.async.cg.shared.global [%0], [%1], 16;" :: "r"(dst), "l"(src))

// ---------------- hi/lo split: [rows][2048] fp32 -> [rows][4096] bf16 --------
__global__ __launch_bounds__(256) void split2_kernel(
    const float* __restrict__ x, __nv_bfloat16* __restrict__ out, int nelem)
{
    int i4 = (blockIdx.x * 256 + threadIdx.x) * 4;
    if (i4 >= nelem) return;
    int r = i4 >> 11, c = i4 & 2047;
    float4 v = *(const float4*)(x + i4);
    __nv_bfloat16 h0 = __float2bfloat16(v.x), h1 = __float2bfloat16(v.y);
    __nv_bfloat16 h2 = __float2bfloat16(v.z), h3 = __float2bfloat16(v.w);
    __nv_bfloat162 H01, H23, L01, L23;
    H01.x = h0; H01.y = h1; H23.x = h2; H23.y = h3;
    L01.x = __float2bfloat16(v.x - __bfloat162float(h0));
    L01.y = __float2bfloat16(v.y - __bfloat162float(h1));
    L23.x = __float2bfloat16(v.z - __bfloat162float(h2));
    L23.y = __float2bfloat16(v.w - __bfloat162float(h3));
    __nv_bfloat16* row = out + (size_t)r * K2_ + c;
    *(__nv_bfloat162*)(row)            = H01;
    *(__nv_bfloat162*)(row + 2)        = H23;
    *(__nv_bfloat162*)(row + 2048)     = L01;
    *(__nv_bfloat162*)(row + 2048 + 2) = L23;
}

// ---------------- mma.sync GEMM with dedup hi/lo 3-pass mainloop ----------------
// C[m,n] = sum_d (ah+al)[m,d]*(wh+wl)[n,d] (drop al*wl). 128x128 tile, 8 warps,
// D-chunk 32 cols, buffers Ahi/Alo/Whi/Wlo per stage, 2 stages, occ 2.
#define LDV 40                        // padded stride (elems) for 32-col buffers
#define BUF_E (128*LDV)               // 5120 elems = 10KB
#define STAGE_E (4*BUF_E)             // Ahi,Alo,Whi,Wlo
#define GEMM_SMEM (2*STAGE_E*2)       // 81920 B
#define NCH2 64                       // 2048/32 chunks

__global__ __launch_bounds__(256, 2) void gemm_mma(
    const __nv_bfloat16* __restrict__ A, const __nv_bfloat16* __restrict__ Wt,
    const float* __restrict__ bias, float* __restrict__ C, int headed)
{
    extern __shared__ __nv_bfloat16 sm[];
    const int tid = threadIdx.x;
    const int lane = tid & 31, w = tid >> 5;
    const int wm = (w >> 2) << 6;            // 0 / 64
    const int wn = (w & 3) << 5;             // 0,32,64,96
    const int m0 = blockIdx.y << 7, n0 = blockIdx.x << 7;

    const __nv_bfloat16* Ag = A  + (size_t)m0 * K2_;
    const __nv_bfloat16* Wg = Wt + (size_t)n0 * K2_;

    float acc[4][4][4];
#pragma unroll
    for (int mi = 0; mi < 4; mi++)
#pragma unroll
        for (int ni = 0; ni < 4; ni++)
#pragma unroll
            for (int j = 0; j < 4; j++) acc[mi][ni][j] = 0.f;

    // loader: per buffer 512 segs of 16B; 256 thr x 2
    const int seg0 = tid, seg1 = tid + 256;
    const int r0 = seg0 >> 2, c0 = (seg0 & 3) << 3;
    const int r1 = seg1 >> 2, c1 = (seg1 & 3) << 3;
#define LOAD_CHUNK2(stage, chunk) do {                                           \
    uint32_t sb = smem_u32(sm + (stage) * STAGE_E);                              \
    const size_t off = (size_t)(chunk) * 32;                                     \
    CPA16(sb + (r0*LDV + c0)*2,             Ag + (size_t)r0*K2_ + off + c0);     \
    CPA16(sb + (r1*LDV + c1)*2,             Ag + (size_t)r1*K2_ + off + c1);     \
    CPA16(sb + (BUF_E + r0*LDV + c0)*2,     Ag + (size_t)r0*K2_ + 2048 + off + c0); \
    CPA16(sb + (BUF_E + r1*LDV + c1)*2,     Ag + (size_t)r1*K2_ + 2048 + off + c1); \
    CPA16(sb + (2*BUF_E + r0*LDV + c0)*2,   Wg + (size_t)r0*K2_ + off + c0);     \
    CPA16(sb + (2*BUF_E + r1*LDV + c1)*2,   Wg + (size_t)r1*K2_ + off + c1);     \
    CPA16(sb + (3*BUF_E + r0*LDV + c0)*2,   Wg + (size_t)r0*K2_ + 2048 + off + c0); \
    CPA16(sb + (3*BUF_E + r1*LDV + c1)*2,   Wg + (size_t)r1*K2_ + 2048 + off + c1); \
    asm volatile("cp.async.commit_group;" ::: "memory");                         \
} while (0)

    LOAD_CHUNK2(0, 0);
    LOAD_CHUNK2(1, 1);

    for (int c = 0; c < NCH2; c++) {
        const int s = c & 1;
        if (c + 1 < NCH2) {
            asm volatile("cp.async.wait_group 1;" ::: "memory");
        } else {
            asm volatile("cp.async.wait_group 0;" ::: "memory");
        }
        __syncthreads();

        const uint32_t sb = smem_u32(sm + s * STAGE_E);
#pragma unroll
        for (int ks = 0; ks < 2; ks++) {
            const int kc = ks << 4;
            uint32_t ah[4][4], al[4][4];
#pragma unroll
            for (int mi = 0; mi < 4; mi++) {
                int r = wm + (mi << 4) + (lane & 15);
                int cc = kc + ((lane >> 4) << 3);
                LDSM4(ah[mi][0], ah[mi][1], ah[mi][2], ah[mi][3], sb + (r*LDV + cc)*2);
                LDSM4(al[mi][0], al[mi][1], al[mi][2], al[mi][3], sb + (BUF_E + r*LDV + cc)*2);
            }
            uint32_t bh[4][2], bl[4][2];
#pragma unroll
            for (int nb = 0; nb < 2; nb++) {
                int r = wn + (nb << 4) + (lane & 7) + (((lane >> 4) & 1) << 3);
                int cc = kc + (((lane >> 3) & 1) << 3);
                LDSM4(bh[nb*2][0], bh[nb*2][1], bh[nb*2+1][0], bh[nb*2+1][1],
                      sb + (2*BUF_E + r*LDV + cc)*2);
                LDSM4(bl[nb*2][0], bl[nb*2][1], bl[nb*2+1][0], bl[nb*2+1][1],
                      sb + (3*BUF_E + r*LDV + cc)*2);
            }
#pragma unroll
            for (int mi = 0; mi < 4; mi++)
#pragma unroll
                for (int ni = 0; ni < 4; ni++) {
                    MMA16816(acc[mi][ni], ah[mi], bh[ni][0], bh[ni][1]);
                    MMA16816(acc[mi][ni], ah[mi], bl[ni][0], bl[ni][1]);
                    MMA16816(acc[mi][ni], al[mi], bh[ni][0], bh[ni][1]);
                }
        }
        __syncthreads();
        if (c + 2 < NCH2) LOAD_CHUNK2(s, c + 2);
    }

#pragma unroll
    for (int mi = 0; mi < 4; mi++) {
#pragma unroll
        for (int half = 0; half < 2; half++) {
            int m = m0 + wm + (mi << 4) + (lane >> 2) + (half << 3);
            float* dst;
#pragma unroll
            for (int ni = 0; ni < 4; ni++) {
                int n = n0 + wn + (ni << 3) + ((lane & 3) << 1);
                float2 o;
                o.x = acc[mi][ni][half*2+0] + bias[n];
                o.y = acc[mi][ni][half*2+1] + bias[n+1];
                if (headed) {
                    int b = m >> 11, sidx = m & (S_ - 1), h = n >> 7, dk = n & (DK_ - 1);
                    dst = C + ((((size_t)b * H_ + h) * S_ + sidx) << 7) + dk;
                } else {
                    dst = C + (size_t)m * D_ + n;
                }
                *(float2*)dst = o;
            }
        }
    }
}

// ---------------- RoPE table ----------------
__global__ __launch_bounds__(256) void rope_table()
{
    int idx = blockIdx.x * blockDim.x + threadIdx.x;
    if (idx >= S_ * 64) return;
    int i = idx & 63;
    int s = idx >> 6;
    float inv = powf(10000.f, -(float)(2 * i) / 128.f);
    float ph  = (float)s * inv;
    g_cos[idx] = cosf(ph);
    g_sin[idx] = sinf(ph);
}

// ---------------- RoPE + hi/lo split for q,k ----------------
__global__ __launch_bounds__(256) void rope_split()
{
    int idx = blockIdx.x * blockDim.x + threadIdx.x;  // BH*S*64
    int i  = idx & 63;
    int s  = (idx >> 6) & (S_ - 1);
    int bh = idx >> 17;
    float c  = g_cos[(s << 6) + i];
    float sn = g_sin[(s << 6) + i];
    size_t base = ((size_t)bh * S_ + s) << 7;

    float q1 = g_q[base + i], q2 = g_q[base + 64 + i];
    float r1 = q1 * c - q2 * sn;
    float r2 = q2 * c + q1 * sn;
    __nv_bfloat16 h1 = __float2bfloat16(r1), h2 = __float2bfloat16(r2);
    g_qh[base + i]      = h1;
    g_qh[base + 64 + i] = h2;
    g_ql[base + i]      = __float2bfloat16(r1 - __bfloat162float(h1));
    g_ql[base + 64 + i] = __float2bfloat16(r2 - __bfloat162float(h2));

    float k1 = g_k[base + i], k2 = g_k[base + 64 + i];
    float t1 = k1 * c - k2 * sn;
    float t2 = k2 * c + k1 * sn;
    __nv_bfloat16 g1 = __float2bfloat16(t1), g2 = __float2bfloat16(t2);
    g_kh[base + i]      = g1;
    g_kh[base + 64 + i] = g2;
    g_kl[base + i]      = __float2bfloat16(t1 - __bfloat162float(g1));
    g_kl[base + 64 + i] = __float2bfloat16(t2 - __bfloat162float(g2));
}

// ---------------- V transpose + split: [bh][s][d] -> [bh][d][s] hi/lo ----------------
__global__ __launch_bounds__(256) void v_split()
{
    __shared__ float smt[32][33];
    int bh = blockIdx.z;
    int s0 = blockIdx.x << 5, d0 = blockIdx.y << 5;
    int tx = threadIdx.x, ty = threadIdx.y;   // (32, 8)
#pragma unroll
    for (int i = 0; i < 4; i++) {
        int r = ty + (i << 3);
        smt[r][tx] = g_v[(((size_t)bh * S_ + s0 + r) << 7) + d0 + tx];
    }
    __syncthreads();
#pragma unroll
    for (int i = 0; i < 4; i++) {
        int dd = ty + (i << 3);
        float v = smt[tx][dd];
        __nv_bfloat16 h = __float2bfloat16(v);
        size_t o = ((size_t)bh * DK_ + d0 + dd) * S_ + s0 + tx;
        g_vth[o] = h;
        g_vtl[o] = __float2bfloat16(v - __bfloat162float(h));
    }
}

// ---------------- tensor-core causal flash attention (bf16x3) ----------------
#define QLD 136
#define VLD 72
#define oQH 0
#define oQL 17408
#define oKV 34816
#define stKV 35840
#define ATTN2_SMEM ((oKV + 2*stKV)*2)   // 212992 B

__global__ __launch_bounds__(256, 1) void attn_mma(
    const __nv_bfloat16* __restrict__ gqh, const __nv_bfloat16* __restrict__ gql,
    const __nv_bfloat16* __restrict__ gkh, const __nv_bfloat16* __restrict__ gkl,
    const __nv_bfloat16* __restrict__ gvh, const __nv_bfloat16* __restrict__ gvl,
    __nv_bfloat16* __restrict__ acat)
{
    extern __shared__ __nv_bfloat16 smb[];
    const uint32_t usm = smem_u32(smb);
    const int tid = threadIdx.x;
    const int lane = tid & 31, w = tid >> 5;
    const int wrow = w << 4;
    const int qt = gridDim.x - 1 - blockIdx.x;     // heavy tiles first
    const int bh = blockIdx.y;
    const int b  = bh >> 4, h = bh & 15;
    const int nblk = 2 * qt + 2;
    const float SCL2 = 0.12751743f;                // 1/sqrt(128) * log2(e)

    const size_t qbase = ((size_t)bh * S_ + (size_t)qt * 128) << 7;

    {
#pragma unroll
        for (int i = 0; i < 8; i++) {
            int ch = tid + (i << 8);
            int r = ch >> 4, c8 = (ch & 15) << 3;
            CPA16(usm + (uint32_t)(oQH + r * QLD + c8) * 2, gqh + qbase + ((size_t)r << 7) + c8);
            CPA16(usm + (uint32_t)(oQL + r * QLD + c8) * 2, gql + qbase + ((size_t)r << 7) + c8);
        }
    }
#define LOAD_KV(stage, jb) do {                                                      \
    uint32_t kvb = oKV + (stage) * stKV;                                             \
    size_t kbase = ((size_t)bh * S_ + (size_t)(jb) * 64) << 7;                       \
    _Pragma("unroll")                                                                \
    for (int i = 0; i < 4; i++) {                                                    \
        int ch = tid + (i << 8);                                                     \
        int r = ch >> 4, c8 = (ch & 15) << 3;                                        \
        CPA16(usm + (kvb + r * QLD + c8) * 2,        gkh + kbase + ((size_t)r << 7) + c8); \
        CPA16(usm + (kvb + 8704 + r * QLD + c8) * 2, gkl + kbase + ((size_t)r << 7) + c8); \
    }                                                                                \
    size_t vbase = ((size_t)bh * DK_) * S_ + (size_t)(jb) * 64;                      \
    _Pragma("unroll")                                                                \
    for (int i = 0; i < 4; i++) {                                                    \
        int ch = tid + (i << 8);                                                     \
        int r = ch >> 3, c8 = (ch & 7) << 3;                                         \
        CPA16(usm + (kvb + 17408 + r * VLD + c8) * 2, gvh + vbase + (size_t)r * S_ + c8); \
        CPA16(usm + (kvb + 26624 + r * VLD + c8) * 2, gvl + vbase + (size_t)r * S_ + c8); \
    }                                                                                \
    asm volatile("cp.async.commit_group;" ::: "memory");                             \
} while (0)

    LOAD_KV(0, 0);
    LOAD_KV(1, 1);

    float oa[16][4];
#pragma unroll
    for (int nt = 0; nt < 16; nt++)
#pragma unroll
        for (int j = 0; j < 4; j++) oa[nt][j] = 0.f;
    float m0r = -1e30f, m1r = -1e30f, l0r = 0.f, l1r = 0.f;

    const int grow0 = qt * 128 + wrow + (lane >> 2);
    const int grow1 = grow0 + 8;

    for (int jb = 0; jb < nblk; jb++) {
        const int st = jb & 1;
        if (jb + 1 < nblk) {
            asm volatile("cp.async.wait_group 1;" ::: "memory");
        } else {
            asm volatile("cp.async.wait_group 0;" ::: "memory");
        }
        __syncthreads();

        const uint32_t kvb = oKV + st * stKV;

        float sa[8][4];
#pragma unroll
        for (int nt = 0; nt < 8; nt++)
#pragma unroll
            for (int j = 0; j < 4; j++) sa[nt][j] = 0.f;

#pragma unroll
        for (int kt = 0; kt < 8; kt++) {
            const int kc = kt << 4;
            uint32_t ah[4], al[4];
            {
                int r = wrow + (lane & 15);
                int cc = kc + ((lane >> 4) << 3);
                LDSM4(ah[0], ah[1], ah[2], ah[3], usm + (uint32_t)(oQH + r * QLD + cc) * 2);
                LDSM4(al[0], al[1], al[2], al[3], usm + (uint32_t)(oQL + r * QLD + cc) * 2);
            }
#pragma unroll
            for (int ntp = 0; ntp < 4; ntp++) {
                int r = (ntp << 4) + (lane & 7) + (((lane >> 4) & 1) << 3);
                int cc = kc + (((lane >> 3) & 1) << 3);
                uint32_t bhh[4], bll[4];
                LDSM4(bhh[0], bhh[1], bhh[2], bhh[3], usm + (kvb + r * QLD + cc) * 2);
                LDSM4(bll[0], bll[1], bll[2], bll[3], usm + (kvb + 8704 + r * QLD + cc) * 2);
#pragma unroll
                for (int t = 0; t < 2; t++) {
                    int nt = (ntp << 1) + t;
                    MMA16816(sa[nt], ah, bhh[2*t], bhh[2*t+1]);
                    MMA16816(sa[nt], ah, bll[2*t], bll[2*t+1]);
                    MMA16816(sa[nt], al, bhh[2*t], bhh[2*t+1]);
                }
            }
        }

        const bool needmask = (jb >= 2 * qt);
#pragma unroll
        for (int nt = 0; nt < 8; nt++) {
            int cb = jb * 64 + (nt << 3) + ((lane & 3) << 1);
#pragma unroll
            for (int j = 0; j < 4; j++) {
                float x = sa[nt][j] * SCL2;
                if (needmask) {
                    int col = cb + (j & 1);
                    int row = (j < 2) ? grow0 : grow1;
                    if (col > row) x = -1e30f;
                }
                sa[nt][j] = x;
            }
        }

        float rm0 = -1e30f, rm1 = -1e30f;
#pragma unroll
        for (int nt = 0; nt < 8; nt++) {
            rm0 = fmaxf(rm0, fmaxf(sa[nt][0], sa[nt][1]));
            rm1 = fmaxf(rm1, fmaxf(sa[nt][2], sa[nt][3]));
        }
        rm0 = fmaxf(rm0, __shfl_xor_sync(0xffffffffu, rm0, 1));
        rm0 = fmaxf(rm0, __shfl_xor_sync(0xffffffffu, rm0, 2));
        rm1 = fmaxf(rm1, __shfl_xor_sync(0xffffffffu, rm1, 1));
        rm1 = fmaxf(rm1, __shfl_xor_sync(0xffffffffu, rm1, 2));
        float mn0 = fmaxf(m0r, rm0), mn1 = fmaxf(m1r, rm1);
        float al0 = exp2f(m0r - mn0), al1 = exp2f(m1r - mn1);
        m0r = mn0; m1r = mn1;

        float rs0 = 0.f, rs1 = 0.f;
#pragma unroll
        for (int nt = 0; nt < 8; nt++) {
            float p0 = exp2f(sa[nt][0] - mn0);
            float p1 = exp2f(sa[nt][1] - mn0);
            float p2 = exp2f(sa[nt][2] - mn1);
            float p3 = exp2f(sa[nt][3] - mn1);
            sa[nt][0] = p0; sa[nt][1] = p1; sa[nt][2] = p2; sa[nt][3] = p3;
            rs0 += p0 + p1; rs1 += p2 + p3;
        }
        rs0 += __shfl_xor_sync(0xffffffffu, rs0, 1);
        rs0 += __shfl_xor_sync(0xffffffffu, rs0, 2);
        rs1 += __shfl_xor_sync(0xffffffffu, rs1, 1);
        rs1 += __shfl_xor_sync(0xffffffffu, rs1, 2);
        l0r = l0r * al0 + rs0;
        l1r = l1r * al1 + rs1;

#pragma unroll
        for (int nt = 0; nt < 16; nt++) {
            oa[nt][0] *= al0; oa[nt][1] *= al0;
            oa[nt][2] *= al1; oa[nt][3] *= al1;
        }

#pragma unroll
        for (int kt2 = 0; kt2 < 4; kt2++) {
            const int t0 = kt2 << 1, t1 = t0 + 1;
            uint32_t pah[4], pal[4];
            {
                __nv_bfloat162 hh, ll;
                float p0, p1, r0, r1;
                p0 = sa[t0][0]; p1 = sa[t0][1];
                hh = __floats2bfloat162_rn(p0, p1);
                r0 = p0 - __bfloat162float(hh.x); r1 = p1 - __bfloat162float(hh.y);
                ll = __floats2bfloat162_rn(r0, r1);
                pah[0] = *(uint32_t*)&hh; pal[0] = *(uint32_t*)&ll;
                p0 = sa[t0][2]; p1 = sa[t0][3];
                hh = __floats2bfloat162_rn(p0, p1);
                r0 = p0 - __bfloat162float(hh.x); r1 = p1 - __bfloat162float(hh.y);
                ll = __floats2bfloat162_rn(r0, r1);
                pah[1] = *(uint32_t*)&hh; pal[1] = *(uint32_t*)&ll;
                p0 = sa[t1][0]; p1 = sa[t1][1];
                hh = __floats2bfloat162_rn(p0, p1);
                r0 = p0 - __bfloat162float(hh.x); r1 = p1 - __bfloat162float(hh.y);
                ll = __floats2bfloat162_rn(r0, r1);
                pah[2] = *(uint32_t*)&hh; pal[2] = *(uint32_t*)&ll;
                p0 = sa[t1][2]; p1 = sa[t1][3];
                hh = __floats2bfloat162_rn(p0, p1);
                r0 = p0 - __bfloat162float(hh.x); r1 = p1 - __bfloat162float(hh.y);
                ll = __floats2bfloat162_rn(r0, r1);
                pah[3] = *(uint32_t*)&hh; pal[3] = *(uint32_t*)&ll;
            }
            const int cv = (kt2 << 4) + (((lane >> 3) & 1) << 3);
#pragma unroll
            for (int ntp = 0; ntp < 8; ntp++) {
                int r = (ntp << 4) + (lane & 7) + (((lane >> 4) & 1) << 3);
                uint32_t vhh[4], vll[4];
                LDSM4(vhh[0], vhh[1], vhh[2], vhh[3], usm + (kvb + 17408 + r * VLD + cv) * 2);
                LDSM4(vll[0], vll[1], vll[2], vll[3], usm + (kvb + 26624 + r * VLD + cv) * 2);
#pragma unroll
                for (int t = 0; t < 2; t++) {
                    int nt = (ntp << 1) + t;
                    MMA16816(oa[nt], pah, vhh[2*t], vhh[2*t+1]);
                    MMA16816(oa[nt], pah, vll[2*t], vll[2*t+1]);
                    MMA16816(oa[nt], pal, vhh[2*t], vhh[2*t+1]);
                }
            }
        }

        __syncthreads();
        if (jb + 2 < nblk) LOAD_KV(st, jb + 2);
    }

    // ---- epilogue: O /= l, hi/lo split written directly into acat [m][4096]
    float inv0 = 1.f / l0r, inv1 = 1.f / l1r;
    int srow0 = qt * 128 + wrow + (lane >> 2);
    int mrow0 = b * S_ + srow0;
    __nv_bfloat16* a0 = acat + (size_t)mrow0 * K2_ + (h << 7);
    __nv_bfloat16* a1 = a0 + (size_t)8 * K2_;
#pragma unroll
    for (int nt = 0; nt < 16; nt++) {
        int cb = (nt << 3) + ((lane & 3) << 1);
        float v00 = oa[nt][0] * inv0, v01 = oa[nt][1] * inv0;
        float v10 = oa[nt][2] * inv1, v11 = oa[nt][3] * inv1;
        __nv_bfloat162 h0 = __floats2bfloat162_rn(v00, v01);
        __nv_bfloat162 l0p = __floats2bfloat162_rn(v00 - __bfloat162float(h0.x),
                                                   v01 - __bfloat162float(h0.y));
        __nv_bfloat162 h1 = __floats2bfloat162_rn(v10, v11);
        __nv_bfloat162 l1p = __floats2bfloat162_rn(v10 - __bfloat162float(h1.x),
                                                   v11 - __bfloat162float(h1.y));
        *(__nv_bfloat162*)(a0 + cb)        = h0;
        *(__nv_bfloat162*)(a0 + 2048 + cb) = l0p;
        *(__nv_bfloat162*)(a1 + cb)        = h1;
        *(__nv_bfloat162*)(a1 + 2048 + cb) = l1p;
    }
}

// ---------------- launch ----------------
extern "C" void kernel_launch(void* const* d_in, const int* in_sizes, int n_in,
                              void* d_out, int out_size)
{
    const float* query = (const float*)d_in[0];
    const float* key   = (const float*)d_in[1];
    const float* value = (const float*)d_in[2];
    const float* wq = (const float*)d_in[4];
    const float* bq = (const float*)d_in[5];
    const float* wk = (const float*)d_in[6];
    const float* bk = (const float*)d_in[7];
    const float* wv = (const float*)d_in[8];
    const float* bv = (const float*)d_in[9];
    const float* wo = (const float*)d_in[10];
    const float* bo = (const float*)d_in[11];
    float* out = (float*)d_out;

    float *q_s, *k_s, *v_s;
    __nv_bfloat16 *acat, *wcat, *qh, *ql, *kh, *kl, *vth, *vtl;
    cudaGetSymbolAddress((void**)&q_s, g_q);
    cudaGetSymbolAddress((void**)&k_s, g_k);
    cudaGetSymbolAddress((void**)&v_s, g_v);
    cudaGetSymbolAddress((void**)&acat, g_acat);
    cudaGetSymbolAddress((void**)&wcat, g_wcat);
    cudaGetSymbolAddress((void**)&qh, g_qh);
    cudaGetSymbolAddress((void**)&ql, g_ql);
    cudaGetSymbolAddress((void**)&kh, g_kh);
    cudaGetSymbolAddress((void**)&kl, g_kl);
    cudaGetSymbolAddress((void**)&vth, g_vth);
    cudaGetSymbolAddress((void**)&vtl, g_vtl);

    cudaFuncSetAttribute(gemm_mma, cudaFuncAttributeMaxDynamicSharedMemorySize, GEMM_SMEM);
    cudaFuncSetAttribute(attn_mma, cudaFuncAttributeMaxDynamicSharedMemorySize, ATTN2_SMEM);

    const int wgrid = (D_ * D_ / 4 + 255) / 256;
    const int agrid = (M_ * D_ / 4 + 255) / 256;
    dim3 ggrid(D_ / 128, M_ / 128);

    // Q projection
    split2_kernel<<<agrid, 256>>>(query, acat, M_ * D_);
    split2_kernel<<<wgrid, 256>>>(wq, wcat, D_ * D_);
    gemm_mma<<<ggrid, 256, GEMM_SMEM>>>(acat, wcat, bq, q_s, 1);
    // K projection
    split2_kernel<<<agrid, 256>>>(key, acat, M_ * D_);
    split2_kernel<<<wgrid, 256>>>(wk, wcat, D_ * D_);
    gemm_mma<<<ggrid, 256, GEMM_SMEM>>>(acat, wcat, bk, k_s, 1);
    // V projection
    split2_kernel<<<agrid, 256>>>(value, acat, M_ * D_);
    split2_kernel<<<wgrid, 256>>>(wv, wcat, D_ * D_);
    gemm_mma<<<ggrid, 256, GEMM_SMEM>>>(acat, wcat, bv, v_s, 1);

    rope_table<<<(S_ * 64) / 256, 256>>>();
    rope_split<<<(BH_ * S_ * 64) / 256, 256>>>();
    v_split<<<dim3(S_ / 32, DK_ / 32, BH_), dim3(32, 8)>>>();

    // attention writes hi/lo split O directly into acat
    attn_mma<<<dim3(S_ / 128, BH_), 256, ATTN2_SMEM>>>(qh, ql, kh, kl, vth, vtl, acat);

    // Output projection
    split2_kernel<<<wgrid, 256>>>(wo, wcat, D_ * D_);
    gemm_mma<<<ggrid, 256, GEMM_SMEM>>>(acat, wcat, bo, out, 0);
}

// round 10
// speedup vs baseline: 3.7974x; 1.2177x over previous
#include <cuda_runtime.h>
#include <cuda_bf16.h>
#include <math.h>
#include <stdint.h>

#define B_  2
#define S_  2048
#define D_  2048
#define H_  16
#define DK_ 128
#define M_  (B_*S_)   // 4096
#define BH_ (B_*H_)   // 32
#define K2_ 4096      // [hi | lo] dedup layout

// ---------------- scratch (device globals; no allocs allowed) ----------------
__device__ __nv_bfloat16 g_acat0[M_*K2_];  // query split / attn-out split
__device__ __nv_bfloat16 g_acat1[M_*K2_];  // key split
__device__ __nv_bfloat16 g_acat2[M_*K2_];  // value split
__device__ __nv_bfloat16 g_wcat0[D_*K2_];  // wq
__device__ __nv_bfloat16 g_wcat1[D_*K2_];  // wk
__device__ __nv_bfloat16 g_wcat2[D_*K2_];  // wv
__device__ __nv_bfloat16 g_wcat3[D_*K2_];  // wo
__device__ float g_q[BH_*S_*DK_];
__device__ float g_k[BH_*S_*DK_];
__device__ float g_v[BH_*S_*DK_];
__device__ float g_cos[S_*64];
__device__ float g_sin[S_*64];
__device__ __nv_bfloat16 g_qh[BH_*S_*DK_], g_ql[BH_*S_*DK_];
__device__ __nv_bfloat16 g_kh[BH_*S_*DK_], g_kl[BH_*S_*DK_];
__device__ __nv_bfloat16 g_vth[BH_*DK_*S_], g_vtl[BH_*DK_*S_];  // [bh][d][s]

__device__ __forceinline__ uint32_t smem_u32(const void* p) {
    uint32_t a;
    asm("{ .reg .u64 t; cvta.to.shared.u64 t, %1; cvt.u32.u64 %0, t; }" : "=r"(a) : "l"(p));
    return a;
}

#define LDSM4(r0,r1,r2,r3, addr) \
    asm volatile("ldmatrix.sync.aligned.m8n8.x4.shared.b16 {%0,%1,%2,%3}, [%4];" \
        : "=r"(r0), "=r"(r1), "=r"(r2), "=r"(r3) : "r"(addr))

#define MMA16816(d, a, b0v, b1v) \
    asm volatile("mma.sync.aligned.m16n8k16.row.col.f32.bf16.bf16.f32 " \
        "{%0,%1,%2,%3}, {%4,%5,%6,%7}, {%8,%9}, {%0,%1,%2,%3};" \
        : "+f"((d)[0]), "+f"((d)[1]), "+f"((d)[2]), "+f"((d)[3]) \
        : "r"((a)[0]), "r"((a)[1]), "r"((a)[2]), "r"((a)[3]), "r"(b0v), "r"(b1v))

#define CPA16(dst, src) \
    asm volatile("cp.async.cg.shared.global [%0], [%1], 16;" :: "r"(dst), "l"(src))

// ---------------- hi/lo split bodies ----------------
__device__ __forceinline__ void split_body(
    const float* __restrict__ x, __nv_bfloat16* __restrict__ out)
{
    int i4 = (blockIdx.x * 256 + threadIdx.x) * 4;
    int r = i4 >> 11, c = i4 & 2047;
    float4 v = *(const float4*)(x + i4);
    __nv_bfloat16 h0 = __float2bfloat16(v.x), h1 = __float2bfloat16(v.y);
    __nv_bfloat16 h2 = __float2bfloat16(v.z), h3 = __float2bfloat16(v.w);
    __nv_bfloat162 H01, H23, L01, L23;
    H01.x = h0; H01.y = h1; H23.x = h2; H23.y = h3;
    L01.x = __float2bfloat16(v.x - __bfloat162float(h0));
    L01.y = __float2bfloat16(v.y - __bfloat162float(h1));
    L23.x = __float2bfloat16(v.z - __bfloat162float(h2));
    L23.y = __float2bfloat16(v.w - __bfloat162float(h3));
    __nv_bfloat16* row = out + (size_t)r * K2_ + c;
    *(__nv_bfloat162*)(row)            = H01;
    *(__nv_bfloat162*)(row + 2)        = H23;
    *(__nv_bfloat162*)(row + 2048)     = L01;
    *(__nv_bfloat162*)(row + 2048 + 2) = L23;
}

__global__ __launch_bounds__(256) void splitA3(
    const float* __restrict__ x0, const float* __restrict__ x1, const float* __restrict__ x2,
    __nv_bfloat16* __restrict__ o0, __nv_bfloat16* __restrict__ o1, __nv_bfloat16* __restrict__ o2)
{
    int z = blockIdx.z;
    split_body(z == 0 ? x0 : (z == 1 ? x1 : x2), z == 0 ? o0 : (z == 1 ? o1 : o2));
}

__global__ __launch_bounds__(256) void splitW4(
    const float* __restrict__ x0, const float* __restrict__ x1,
    const float* __restrict__ x2, const float* __restrict__ x3,
    __nv_bfloat16* __restrict__ o0, __nv_bfloat16* __restrict__ o1,
    __nv_bfloat16* __restrict__ o2, __nv_bfloat16* __restrict__ o3)
{
    int z = blockIdx.z;
    const float* x = z == 0 ? x0 : (z == 1 ? x1 : (z == 2 ? x2 : x3));
    __nv_bfloat16* o = z == 0 ? o0 : (z == 1 ? o1 : (z == 2 ? o2 : o3));
    split_body(x, o);
}

// ---------------- mma.sync GEMM: 3-stage ring, XOR-swizzled 32-col buffers ----
// Buffer: 128 rows x 32 cols (64 B/row), 16B chunk cI at phys (cI ^ ((r>>1)&3)).
// Conflict-free ldmatrix, 16B-aligned cp.async. Stage = 4 bufs = 32 KB.
#define BUF_B 8192                    // bytes per buffer (128*64)
#define STAGE_B (4*BUF_B)             // 32768 B: Ahi,Alo,Whi,Wlo
#define NSTG 3
#define GEMM_SMEM (NSTG*STAGE_B)      // 98304 B (occ 2)
#define NCH2 64                       // 2048/32 chunks
#define SWX(r, cI) ((uint32_t)((r)*64 + ((((cI) ^ (((r)>>1)&3)) & 3) << 4)))

__device__ __forceinline__ void gemm_body(
    const __nv_bfloat16* __restrict__ A, const __nv_bfloat16* __restrict__ Wt,
    const float* __restrict__ bias, float* __restrict__ C, int headed)
{
    extern __shared__ __nv_bfloat16 sm[];
    const int tid = threadIdx.x;
    const int lane = tid & 31, w = tid >> 5;
    const int wm = (w >> 2) << 6;            // 0 / 64
    const int wn = (w & 3) << 5;             // 0,32,64,96
    const int m0 = blockIdx.y << 7, n0 = blockIdx.x << 7;

    const __nv_bfloat16* Ag = A  + (size_t)m0 * K2_;
    const __nv_bfloat16* Wg = Wt + (size_t)n0 * K2_;

    float acc[4][4][4];
#pragma unroll
    for (int mi = 0; mi < 4; mi++)
#pragma unroll
        for (int ni = 0; ni < 4; ni++)
#pragma unroll
            for (int j = 0; j < 4; j++) acc[mi][ni][j] = 0.f;

    // loader: buffer = 512 chunks of 16B; thread handles chunks tid and tid+256
    const int r0 = tid >> 2,        cI0 = tid & 3;          // rows 0..63
    const int r1 = (tid >> 2) + 64, cI1 = tid & 3;          // rows 64..127
    const uint32_t so0 = SWX(r0, cI0), so1 = SWX(r1, cI1);
    const int e0 = cI0 << 3, e1 = cI1 << 3;                 // elem offset in row
#define LOAD_CHUNK2(stage, chunk) do {                                           \
    uint32_t sb = smem_u32((const char*)sm + (stage) * STAGE_B);                 \
    const size_t off = (size_t)(chunk) * 32;                                     \
    CPA16(sb + so0,            Ag + (size_t)r0*K2_ + off + e0);                  \
    CPA16(sb + so1,            Ag + (size_t)r1*K2_ + off + e1);                  \
    CPA16(sb + BUF_B + so0,    Ag + (size_t)r0*K2_ + 2048 + off + e0);           \
    CPA16(sb + BUF_B + so1,    Ag + (size_t)r1*K2_ + 2048 + off + e1);           \
    CPA16(sb + 2*BUF_B + so0,  Wg + (size_t)r0*K2_ + off + e0);                  \
    CPA16(sb + 2*BUF_B + so1,  Wg + (size_t)r1*K2_ + off + e1);                  \
    CPA16(sb + 3*BUF_B + so0,  Wg + (size_t)r0*K2_ + 2048 + off + e0);           \
    CPA16(sb + 3*BUF_B + so1,  Wg + (size_t)r1*K2_ + 2048 + off + e1);           \
    asm volatile("cp.async.commit_group;" ::: "memory");                         \
} while (0)

    LOAD_CHUNK2(0, 0);
    LOAD_CHUNK2(1, 1);

    for (int c = 0; c < NCH2; c++) {
        const int s = c % NSTG;
        if (c + 1 < NCH2) {
            asm volatile("cp.async.wait_group 1;" ::: "memory");
        } else {
            asm volatile("cp.async.wait_group 0;" ::: "memory");
        }
        __syncthreads();   // chunk c resident; all warps finished chunk c-1

        if (c + 2 < NCH2) LOAD_CHUNK2((c + 2) % NSTG, c + 2);

        const uint32_t sb = smem_u32((const char*)sm + s * STAGE_B);
#pragma unroll
        for (int ks = 0; ks < 2; ks++) {
            const int kbase = ks << 1;                     // chunk pair base (0 or 2)
            uint32_t ah[4][4], al[4][4];
#pragma unroll
            for (int mi = 0; mi < 4; mi++) {
                int r = wm + (mi << 4) + (lane & 15);
                int cI = kbase + (lane >> 4);              // lanes16-31 -> next 16B
                uint32_t off = SWX(r, cI);
                LDSM4(ah[mi][0], ah[mi][1], ah[mi][2], ah[mi][3], sb + off);
                LDSM4(al[mi][0], al[mi][1], al[mi][2], al[mi][3], sb + BUF_B + off);
            }
            uint32_t bh[4][2], bl[4][2];
#pragma unroll
            for (int nb = 0; nb < 2; nb++) {
                int r = wn + (nb << 4) + (lane & 7) + (((lane >> 4) & 1) << 3);
                int cI = kbase + ((lane >> 3) & 1);
                uint32_t off = SWX(r, cI);
                LDSM4(bh[nb*2][0], bh[nb*2][1], bh[nb*2+1][0], bh[nb*2+1][1],
                      sb + 2*BUF_B + off);
                LDSM4(bl[nb*2][0], bl[nb*2][1], bl[nb*2+1][0], bl[nb*2+1][1],
                      sb + 3*BUF_B + off);
            }
#pragma unroll
            for (int mi = 0; mi < 4; mi++)
#pragma unroll
                for (int ni = 0; ni < 4; ni++) {
                    MMA16816(acc[mi][ni], ah[mi], bh[ni][0], bh[ni][1]);
                    MMA16816(acc[mi][ni], ah[mi], bl[ni][0], bl[ni][1]);
                    MMA16816(acc[mi][ni], al[mi], bh[ni][0], bh[ni][1]);
                }
        }
    }

#pragma unroll
    for (int mi = 0; mi < 4; mi++) {
#pragma unroll
        for (int half = 0; half < 2; half++) {
            int m = m0 + wm + (mi << 4) + (lane >> 2) + (half << 3);
            float* dst;
#pragma unroll
            for (int ni = 0; ni < 4; ni++) {
                int n = n0 + wn + (ni << 3) + ((lane & 3) << 1);
                float2 o;
                o.x = acc[mi][ni][half*2+0] + bias[n];
                o.y = acc[mi][ni][half*2+1] + bias[n+1];
                if (headed) {
                    int b = m >> 11, sidx = m & (S_ - 1), h = n >> 7, dk = n & (DK_ - 1);
                    dst = C + ((((size_t)b * H_ + h) * S_ + sidx) << 7) + dk;
                } else {
                    dst = C + (size_t)m * D_ + n;
                }
                *(float2*)dst = o;
            }
        }
    }
}

__global__ __launch_bounds__(256, 2) void gemm_qkv(
    const __nv_bfloat16* a0, const __nv_bfloat16* a1, const __nv_bfloat16* a2,
    const __nv_bfloat16* w0, const __nv_bfloat16* w1, const __nv_bfloat16* w2,
    const float* b0, const float* b1, const float* b2,
    float* d0, float* d1, float* d2)
{
    int z = blockIdx.z;
    const __nv_bfloat16* A = z == 0 ? a0 : (z == 1 ? a1 : a2);
    const __nv_bfloat16* W = z == 0 ? w0 : (z == 1 ? w1 : w2);
    const float* bias = z == 0 ? b0 : (z == 1 ? b1 : b2);
    float* C = z == 0 ? d0 : (z == 1 ? d1 : d2);
    gemm_body(A, W, bias, C, 1);
}

__global__ __launch_bounds__(256, 2) void gemm_out(
    const __nv_bfloat16* A, const __nv_bfloat16* W, const float* bias, float* C)
{
    gemm_body(A, W, bias, C, 0);
}

// ---------------- RoPE table ----------------
__global__ __launch_bounds__(256) void rope_table()
{
    int idx = blockIdx.x * blockDim.x + threadIdx.x;
    if (idx >= S_ * 64) return;
    int i = idx & 63;
    int s = idx >> 6;
    float inv = powf(10000.f, -(float)(2 * i) / 128.f);
    float ph  = (float)s * inv;
    g_cos[idx] = cosf(ph);
    g_sin[idx] = sinf(ph);
}

// ---------------- RoPE + hi/lo split for q,k ----------------
__global__ __launch_bounds__(256) void rope_split()
{
    int idx = blockIdx.x * blockDim.x + threadIdx.x;  // BH*S*64
    int i  = idx & 63;
    int s  = (idx >> 6) & (S_ - 1);
    int bh = idx >> 17;
    float c  = g_cos[(s << 6) + i];
    float sn = g_sin[(s << 6) + i];
    size_t base = ((size_t)bh * S_ + s) << 7;

    float q1 = g_q[base + i], q2 = g_q[base + 64 + i];
    float r1 = q1 * c - q2 * sn;
    float r2 = q2 * c + q1 * sn;
    __nv_bfloat16 h1 = __float2bfloat16(r1), h2 = __float2bfloat16(r2);
    g_qh[base + i]      = h1;
    g_qh[base + 64 + i] = h2;
    g_ql[base + i]      = __float2bfloat16(r1 - __bfloat162float(h1));
    g_ql[base + 64 + i] = __float2bfloat16(r2 - __bfloat162float(h2));

    float k1 = g_k[base + i], k2 = g_k[base + 64 + i];
    float t1 = k1 * c - k2 * sn;
    float t2 = k2 * c + k1 * sn;
    __nv_bfloat16 g1 = __float2bfloat16(t1), g2 = __float2bfloat16(t2);
    g_kh[base + i]      = g1;
    g_kh[base + 64 + i] = g2;
    g_kl[base + i]      = __float2bfloat16(t1 - __bfloat162float(g1));
    g_kl[base + 64 + i] = __float2bfloat16(t2 - __bfloat162float(g2));
}

// ---------------- V transpose + split ----------------
__global__ __launch_bounds__(256) void v_split()
{
    __shared__ float smt[32][33];
    int bh = blockIdx.z;
    int s0 = blockIdx.x << 5, d0 = blockIdx.y << 5;
    int tx = threadIdx.x, ty = threadIdx.y;   // (32, 8)
#pragma unroll
    for (int i = 0; i < 4; i++) {
        int r = ty + (i << 3);
        smt[r][tx] = g_v[(((size_t)bh * S_ + s0 + r) << 7) + d0 + tx];
    }
    __syncthreads();
#pragma unroll
    for (int i = 0; i < 4; i++) {
        int dd = ty + (i << 3);
        float v = smt[tx][dd];
        __nv_bfloat16 h = __float2bfloat16(v);
        size_t o = ((size_t)bh * DK_ + d0 + dd) * S_ + s0 + tx;
        g_vth[o] = h;
        g_vtl[o] = __float2bfloat16(v - __bfloat162float(h));
    }
}

// ---------------- tensor-core causal flash attention (bf16x3) ----------------
#define QLD 136
#define VLD 72
#define oQH 0
#define oQL 17408
#define oKV 34816
#define stKV 35840
#define ATTN2_SMEM ((oKV + 2*stKV)*2)   // 212992 B

__global__ __launch_bounds__(256, 1) void attn_mma(
    const __nv_bfloat16* __restrict__ gqh, const __nv_bfloat16* __restrict__ gql,
    const __nv_bfloat16* __restrict__ gkh, const __nv_bfloat16* __restrict__ gkl,
    const __nv_bfloat16* __restrict__ gvh, const __nv_bfloat16* __restrict__ gvl,
    __nv_bfloat16* __restrict__ acat)
{
    extern __shared__ __nv_bfloat16 smb[];
    const uint32_t usm = smem_u32(smb);
    const int tid = threadIdx.x;
    const int lane = tid & 31, w = tid >> 5;
    const int wrow = w << 4;
    const int qt = gridDim.x - 1 - blockIdx.x;
    const int bh = blockIdx.y;
    const int b  = bh >> 4, h = bh & 15;
    const int nblk = 2 * qt + 2;
    const float SCL2 = 0.12751743f;

    const size_t qbase = ((size_t)bh * S_ + (size_t)qt * 128) << 7;

    {
#pragma unroll
        for (int i = 0; i < 8; i++) {
            int ch = tid + (i << 8);
            int r = ch >> 4, c8 = (ch & 15) << 3;
            CPA16(usm + (uint32_t)(oQH + r * QLD + c8) * 2, gqh + qbase + ((size_t)r << 7) + c8);
            CPA16(usm + (uint32_t)(oQL + r * QLD + c8) * 2, gql + qbase + ((size_t)r << 7) + c8);
        }
    }
#define LOAD_KV(stage, jb) do {                                                      \
    uint32_t kvb = oKV + (stage) * stKV;                                             \
    size_t kbase = ((size_t)bh * S_ + (size_t)(jb) * 64) << 7;                       \
    _Pragma("unroll")                                                                \
    for (int i = 0; i < 4; i++) {                                                    \
        int ch = tid + (i << 8);                                                     \
        int r = ch >> 4, c8 = (ch & 15) << 3;                                        \
        CPA16(usm + (kvb + r * QLD + c8) * 2,        gkh + kbase + ((size_t)r << 7) + c8); \
        CPA16(usm + (kvb + 8704 + r * QLD + c8) * 2, gkl + kbase + ((size_t)r << 7) + c8); \
    }                                                                                \
    size_t vbase = ((size_t)bh * DK_) * S_ + (size_t)(jb) * 64;                      \
    _Pragma("unroll")                                                                \
    for (int i = 0; i < 4; i++) {                                                    \
        int ch = tid + (i << 8);                                                     \
        int r = ch >> 3, c8 = (ch & 7) << 3;                                         \
        CPA16(usm + (kvb + 17408 + r * VLD + c8) * 2, gvh + vbase + (size_t)r * S_ + c8); \
        CPA16(usm + (kvb + 26624 + r * VLD + c8) * 2, gvl + vbase + (size_t)r * S_ + c8); \
    }                                                                                \
    asm volatile("cp.async.commit_group;" ::: "memory");                             \
} while (0)

    LOAD_KV(0, 0);
    LOAD_KV(1, 1);

    float oa[16][4];
#pragma unroll
    for (int nt = 0; nt < 16; nt++)
#pragma unroll
        for (int j = 0; j < 4; j++) oa[nt][j] = 0.f;
    float m0r = -1e30f, m1r = -1e30f, l0r = 0.f, l1r = 0.f;

    const int grow0 = qt * 128 + wrow + (lane >> 2);
    const int grow1 = grow0 + 8;

    for (int jb = 0; jb < nblk; jb++) {
        const int st = jb & 1;
        if (jb + 1 < nblk) {
            asm volatile("cp.async.wait_group 1;" ::: "memory");
        } else {
            asm volatile("cp.async.wait_group 0;" ::: "memory");
        }
        __syncthreads();

        const uint32_t kvb = oKV + st * stKV;

        float sa[8][4];
#pragma unroll
        for (int nt = 0; nt < 8; nt++)
#pragma unroll
            for (int j = 0; j < 4; j++) sa[nt][j] = 0.f;

#pragma unroll
        for (int kt = 0; kt < 8; kt++) {
            const int kc = kt << 4;
            uint32_t ah[4], al[4];
            {
                int r = wrow + (lane & 15);
                int cc = kc + ((lane >> 4) << 3);
                LDSM4(ah[0], ah[1], ah[2], ah[3], usm + (uint32_t)(oQH + r * QLD + cc) * 2);
                LDSM4(al[0], al[1], al[2], al[3], usm + (uint32_t)(oQL + r * QLD + cc) * 2);
            }
#pragma unroll
            for (int ntp = 0; ntp < 4; ntp++) {
                int r = (ntp << 4) + (lane & 7) + (((lane >> 4) & 1) << 3);
                int cc = kc + (((lane >> 3) & 1) << 3);
                uint32_t bhh[4], bll[4];
                LDSM4(bhh[0], bhh[1], bhh[2], bhh[3], usm + (kvb + r * QLD + cc) * 2);
                LDSM4(bll[0], bll[1], bll[2], bll[3], usm + (kvb + 8704 + r * QLD + cc) * 2);
#pragma unroll
                for (int t = 0; t < 2; t++) {
                    int nt = (ntp << 1) + t;
                    MMA16816(sa[nt], ah, bhh[2*t], bhh[2*t+1]);
                    MMA16816(sa[nt], ah, bll[2*t], bll[2*t+1]);
                    MMA16816(sa[nt], al, bhh[2*t], bhh[2*t+1]);
                }
            }
        }

        const bool needmask = (jb >= 2 * qt);
#pragma unroll
        for (int nt = 0; nt < 8; nt++) {
            int cb = jb * 64 + (nt << 3) + ((lane & 3) << 1);
#pragma unroll
            for (int j = 0; j < 4; j++) {
                float x = sa[nt][j] * SCL2;
                if (needmask) {
                    int col = cb + (j & 1);
                    int row = (j < 2) ? grow0 : grow1;
                    if (col > row) x = -1e30f;
                }
                sa[nt][j] = x;
            }
        }

        float rm0 = -1e30f, rm1 = -1e30f;
#pragma unroll
        for (int nt = 0; nt < 8; nt++) {
            rm0 = fmaxf(rm0, fmaxf(sa[nt][0], sa[nt][1]));
            rm1 = fmaxf(rm1, fmaxf(sa[nt][2], sa[nt][3]));
        }
        rm0 = fmaxf(rm0, __shfl_xor_sync(0xffffffffu, rm0, 1));
        rm0 = fmaxf(rm0, __shfl_xor_sync(0xffffffffu, rm0, 2));
        rm1 = fmaxf(rm1, __shfl_xor_sync(0xffffffffu, rm1, 1));
        rm1 = fmaxf(rm1, __shfl_xor_sync(0xffffffffu, rm1, 2));
        float mn0 = fmaxf(m0r, rm0), mn1 = fmaxf(m1r, rm1);
        float al0 = exp2f(m0r - mn0), al1 = exp2f(m1r - mn1);
        m0r = mn0; m1r = mn1;

        float rs0 = 0.f, rs1 = 0.f;
#pragma unroll
        for (int nt = 0; nt < 8; nt++) {
            float p0 = exp2f(sa[nt][0] - mn0);
            float p1 = exp2f(sa[nt][1] - mn0);
            float p2 = exp2f(sa[nt][2] - mn1);
            float p3 = exp2f(sa[nt][3] - mn1);
            sa[nt][0] = p0; sa[nt][1] = p1; sa[nt][2] = p2; sa[nt][3] = p3;
            rs0 += p0 + p1; rs1 += p2 + p3;
        }
        rs0 += __shfl_xor_sync(0xffffffffu, rs0, 1);
        rs0 += __shfl_xor_sync(0xffffffffu, rs0, 2);
        rs1 += __shfl_xor_sync(0xffffffffu, rs1, 1);
        rs1 += __shfl_xor_sync(0xffffffffu, rs1, 2);
        l0r = l0r * al0 + rs0;
        l1r = l1r * al1 + rs1;

#pragma unroll
        for (int nt = 0; nt < 16; nt++) {
            oa[nt][0] *= al0; oa[nt][1] *= al0;
            oa[nt][2] *= al1; oa[nt][3] *= al1;
        }

#pragma unroll
        for (int kt2 = 0; kt2 < 4; kt2++) {
            const int t0 = kt2 << 1, t1 = t0 + 1;
            uint32_t pah[4], pal[4];
            {
                __nv_bfloat162 hh, ll;
                float p0, p1, r0, r1;
                p0 = sa[t0][0]; p1 = sa[t0][1];
                hh = __floats2bfloat162_rn(p0, p1);
                r0 = p0 - __bfloat162float(hh.x); r1 = p1 - __bfloat162float(hh.y);
                ll = __floats2bfloat162_rn(r0, r1);
                pah[0] = *(uint32_t*)&hh; pal[0] = *(uint32_t*)&ll;
                p0 = sa[t0][2]; p1 = sa[t0][3];
                hh = __floats2bfloat162_rn(p0, p1);
                r0 = p0 - __bfloat162float(hh.x); r1 = p1 - __bfloat162float(hh.y);
                ll = __floats2bfloat162_rn(r0, r1);
                pah[1] = *(uint32_t*)&hh; pal[1] = *(uint32_t*)&ll;
                p0 = sa[t1][0]; p1 = sa[t1][1];
                hh = __floats2bfloat162_rn(p0, p1);
                r0 = p0 - __bfloat162float(hh.x); r1 = p1 - __bfloat162float(hh.y);
                ll = __floats2bfloat162_rn(r0, r1);
                pah[2] = *(uint32_t*)&hh; pal[2] = *(uint32_t*)&ll;
                p0 = sa[t1][2]; p1 = sa[t1][3];
                hh = __floats2bfloat162_rn(p0, p1);
                r0 = p0 - __bfloat162float(hh.x); r1 = p1 - __bfloat162float(hh.y);
                ll = __floats2bfloat162_rn(r0, r1);
                pah[3] = *(uint32_t*)&hh; pal[3] = *(uint32_t*)&ll;
            }
            const int cv = (kt2 << 4) + (((lane >> 3) & 1) << 3);
#pragma unroll
            for (int ntp = 0; ntp < 8; ntp++) {
                int r = (ntp << 4) + (lane & 7) + (((lane >> 4) & 1) << 3);
                uint32_t vhh[4], vll[4];
                LDSM4(vhh[0], vhh[1], vhh[2], vhh[3], usm + (kvb + 17408 + r * VLD + cv) * 2);
                LDSM4(vll[0], vll[1], vll[2], vll[3], usm + (kvb + 26624 + r * VLD + cv) * 2);
#pragma unroll
                for (int t = 0; t < 2; t++) {
                    int nt = (ntp << 1) + t;
                    MMA16816(oa[nt], pah, vhh[2*t], vhh[2*t+1]);
                    MMA16816(oa[nt], pah, vll[2*t], vll[2*t+1]);
                    MMA16816(oa[nt], pal, vhh[2*t], vhh[2*t+1]);
                }
            }
        }

        __syncthreads();
        if (jb + 2 < nblk) LOAD_KV(st, jb + 2);
    }

    float inv0 = 1.f / l0r, inv1 = 1.f / l1r;
    int srow0 = qt * 128 + wrow + (lane >> 2);
    int mrow0 = b * S_ + srow0;
    __nv_bfloat16* a0 = acat + (size_t)mrow0 * K2_ + (h << 7);
    __nv_bfloat16* a1 = a0 + (size_t)8 * K2_;
#pragma unroll
    for (int nt = 0; nt < 16; nt++) {
        int cb = (nt << 3) + ((lane & 3) << 1);
        float v00 = oa[nt][0] * inv0, v01 = oa[nt][1] * inv0;
        float v10 = oa[nt][2] * inv1, v11 = oa[nt][3] * inv1;
        __nv_bfloat162 h0 = __floats2bfloat162_rn(v00, v01);
        __nv_bfloat162 l0p = __floats2bfloat162_rn(v00 - __bfloat162float(h0.x),
                                                   v01 - __bfloat162float(h0.y));
        __nv_bfloat162 h1 = __floats2bfloat162_rn(v10, v11);
        __nv_bfloat162 l1p = __floats2bfloat162_rn(v10 - __bfloat162float(h1.x),
                                                   v11 - __bfloat162float(h1.y));
        *(__nv_bfloat162*)(a0 + cb)        = h0;
        *(__nv_bfloat162*)(a0 + 2048 + cb) = l0p;
        *(__nv_bfloat162*)(a1 + cb)        = h1;
        *(__nv_bfloat162*)(a1 + 2048 + cb) = l1p;
    }
}

// ---------------- launch ----------------
extern "C" void kernel_launch(void* const* d_in, const int* in_sizes, int n_in,
                              void* d_out, int out_size)
{
    const float* query = (const float*)d_in[0];
    const float* key   = (const float*)d_in[1];
    const float* value = (const float*)d_in[2];
    const float* wq = (const float*)d_in[4];
    const float* bq = (const float*)d_in[5];
    const float* wk = (const float*)d_in[6];
    const float* bk = (const float*)d_in[7];
    const float* wv = (const float*)d_in[8];
    const float* bv = (const float*)d_in[9];
    const float* wo = (const float*)d_in[10];
    const float* bo = (const float*)d_in[11];
    float* out = (float*)d_out;

    float *q_s, *k_s, *v_s;
    __nv_bfloat16 *ac0, *ac1, *ac2, *wc0, *wc1, *wc2, *wc3;
    __nv_bfloat16 *qh, *ql, *kh, *kl, *vth, *vtl;
    cudaGetSymbolAddress((void**)&q_s, g_q);
    cudaGetSymbolAddress((void**)&k_s, g_k);
    cudaGetSymbolAddress((void**)&v_s, g_v);
    cudaGetSymbolAddress((void**)&ac0, g_acat0);
    cudaGetSymbolAddress((void**)&ac1, g_acat1);
    cudaGetSymbolAddress((void**)&ac2, g_acat2);
    cudaGetSymbolAddress((void**)&wc0, g_wcat0);
    cudaGetSymbolAddress((void**)&wc1, g_wcat1);
    cudaGetSymbolAddress((void**)&wc2, g_wcat2);
    cudaGetSymbolAddress((void**)&wc3, g_wcat3);
    cudaGetSymbolAddress((void**)&qh, g_qh);
    cudaGetSymbolAddress((void**)&ql, g_ql);
    cudaGetSymbolAddress((void**)&kh, g_kh);
    cudaGetSymbolAddress((void**)&kl, g_kl);
    cudaGetSymbolAddress((void**)&vth, g_vth);
    cudaGetSymbolAddress((void**)&vtl, g_vtl);

    cudaFuncSetAttribute(gemm_qkv, cudaFuncAttributeMaxDynamicSharedMemorySize, GEMM_SMEM);
    cudaFuncSetAttribute(gemm_out, cudaFuncAttributeMaxDynamicSharedMemorySize, GEMM_SMEM);
    cudaFuncSetAttribute(attn_mma, cudaFuncAttributeMaxDynamicSharedMemorySize, ATTN2_SMEM);

    // splits (merged)
    splitW4<<<dim3(D_*D_/1024, 1, 4), 256>>>(wq, wk, wv, wo, wc0, wc1, wc2, wc3);
    splitA3<<<dim3(M_*D_/1024, 1, 3), 256>>>(query, key, value, ac0, ac1, ac2);

    // Q,K,V projections in one launch
    gemm_qkv<<<dim3(D_/128, M_/128, 3), 256, GEMM_SMEM>>>(
        ac0, ac1, ac2, wc0, wc1, wc2, bq, bk, bv, q_s, k_s, v_s);

    rope_table<<<(S_ * 64) / 256, 256>>>();
    rope_split<<<(BH_ * S_ * 64) / 256, 256>>>();
    v_split<<<dim3(S_ / 32, DK_ / 32, BH_), dim3(32, 8)>>>();

    // attention writes hi/lo split O directly into ac0
    attn_mma<<<dim3(S_ / 128, BH_), 256, ATTN2_SMEM>>>(qh, ql, kh, kl, vth, vtl, ac0);

    // output projection
    gemm_out<<<dim3(D_/128, M_/128), 256, GEMM_SMEM>>>(ac0, wc3, bo, out);
}

// round 11
// speedup vs baseline: 3.8589x; 1.0162x over previous
#include <cuda_runtime.h>
#include <cuda_bf16.h>
#include <math.h>
#include <stdint.h>

#define B_  2
#define S_  2048
#define D_  2048
#define H_  16
#define DK_ 128
#define M_  (B_*S_)   // 4096
#define BH_ (B_*H_)   // 32
#define K2_ 4096      // [hi | lo] dedup layout

// ---------------- scratch (device globals; no allocs allowed) ----------------
__device__ __nv_bfloat16 g_acat0[M_*K2_];  // query split / attn-out split
__device__ __nv_bfloat16 g_acat1[M_*K2_];  // key split
__device__ __nv_bfloat16 g_acat2[M_*K2_];  // value split
__device__ __nv_bfloat16 g_wcat0[D_*K2_];  // wq
__device__ __nv_bfloat16 g_wcat1[D_*K2_];  // wk
__device__ __nv_bfloat16 g_wcat2[D_*K2_];  // wv
__device__ __nv_bfloat16 g_wcat3[D_*K2_];  // wo
__device__ float g_cos[S_*64];
__device__ float g_sin[S_*64];
__device__ __nv_bfloat16 g_qh[BH_*S_*DK_], g_ql[BH_*S_*DK_];
__device__ __nv_bfloat16 g_kh[BH_*S_*DK_], g_kl[BH_*S_*DK_];
__device__ __nv_bfloat16 g_vth[BH_*DK_*S_], g_vtl[BH_*DK_*S_];  // [bh][d][s]

__device__ __forceinline__ uint32_t smem_u32(const void* p) {
    uint32_t a;
    asm("{ .reg .u64 t; cvta.to.shared.u64 t, %1; cvt.u32.u64 %0, t; }" : "=r"(a) : "l"(p));
    return a;
}

#define LDSM4(r0,r1,r2,r3, addr) \
    asm volatile("ldmatrix.sync.aligned.m8n8.x4.shared.b16 {%0,%1,%2,%3}, [%4];" \
        : "=r"(r0), "=r"(r1), "=r"(r2), "=r"(r3) : "r"(addr))

#define MMA16816(d, a, b0v, b1v) \
    asm volatile("mma.sync.aligned.m16n8k16.row.col.f32.bf16.bf16.f32 " \
        "{%0,%1,%2,%3}, {%4,%5,%6,%7}, {%8,%9}, {%0,%1,%2,%3};" \
        : "+f"((d)[0]), "+f"((d)[1]), "+f"((d)[2]), "+f"((d)[3]) \
        : "r"((a)[0]), "r"((a)[1]), "r"((a)[2]), "r"((a)[3]), "r"(b0v), "r"(b1v))

#define CPA16(dst, src) \
    asm volatile("cp.async.cg.shared.global [%0], [%1], 16;" :: "r"(dst), "l"(src))

// ---------------- hi/lo split (all 7 jobs in one launch) ----------------
__device__ __forceinline__ void split_body(
    const float* __restrict__ x, __nv_bfloat16* __restrict__ out, int lb)
{
    int i4 = (lb * 256 + threadIdx.x) * 4;
    int r = i4 >> 11, c = i4 & 2047;
    float4 v = *(const float4*)(x + i4);
    __nv_bfloat16 h0 = __float2bfloat16(v.x), h1 = __float2bfloat16(v.y);
    __nv_bfloat16 h2 = __float2bfloat16(v.z), h3 = __float2bfloat16(v.w);
    __nv_bfloat162 H01, H23, L01, L23;
    H01.x = h0; H01.y = h1; H23.x = h2; H23.y = h3;
    L01.x = __float2bfloat16(v.x - __bfloat162float(h0));
    L01.y = __float2bfloat16(v.y - __bfloat162float(h1));
    L23.x = __float2bfloat16(v.z - __bfloat162float(h2));
    L23.y = __float2bfloat16(v.w - __bfloat162float(h3));
    __nv_bfloat16* row = out + (size_t)r * K2_ + c;
    *(__nv_bfloat162*)(row)            = H01;
    *(__nv_bfloat162*)(row + 2)        = H23;
    *(__nv_bfloat162*)(row + 2048)     = L01;
    *(__nv_bfloat162*)(row + 2048 + 2) = L23;
}

// blocks: [0,8192) q->ac0, [8192,16384) k->ac1, [16384,24576) v->ac2,
//         then 4x4096 for wq,wk,wv,wo
__global__ __launch_bounds__(256) void split_all(
    const float* q, const float* k, const float* v,
    const float* wq, const float* wk, const float* wv, const float* wo,
    __nv_bfloat16* a0, __nv_bfloat16* a1, __nv_bfloat16* a2,
    __nv_bfloat16* w0, __nv_bfloat16* w1, __nv_bfloat16* w2, __nv_bfloat16* w3)
{
    int bx = blockIdx.x;
    if (bx < 8192)        split_body(q, a0, bx);
    else if (bx < 16384)  split_body(k, a1, bx - 8192);
    else if (bx < 24576)  split_body(v, a2, bx - 16384);
    else {
        int t = bx - 24576, z = t >> 12, lb = t & 4095;
        const float* x = z == 0 ? wq : (z == 1 ? wk : (z == 2 ? wv : wo));
        __nv_bfloat16* o = z == 0 ? w0 : (z == 1 ? w1 : (z == 2 ? w2 : w3));
        split_body(x, o, lb);
    }
}

// ---------------- RoPE table ----------------
__global__ __launch_bounds__(256) void rope_table()
{
    int idx = blockIdx.x * blockDim.x + threadIdx.x;
    if (idx >= S_ * 64) return;
    int i = idx & 63;
    int s = idx >> 6;
    float inv = powf(10000.f, -(float)(2 * i) / 128.f);
    float ph  = (float)s * inv;
    g_cos[idx] = cosf(ph);
    g_sin[idx] = sinf(ph);
}

// ---------------- mma.sync GEMM: 3-stage ring, XOR-swizzled 32-col buffers ----
// mode 0: plain row-major fp32 out. mode 1: rope + hi/lo split -> bh_out/bl_out
// ([bh][s][128] layout). mode 2: transpose + hi/lo split -> vth/vtl ([bh][d][s]).
#define BUF_B 8192
#define STAGE_B (4*BUF_B)
#define NSTG 3
#define GEMM_SMEM (NSTG*STAGE_B)      // 98304 B (occ 2)
#define NCH2 64
#define SWX(r, cI) ((uint32_t)((r)*64 + ((((cI) ^ (((r)>>1)&3)) & 3) << 4)))
#define LDE 133                       // fp32 staging stride (conflict-free both ways)

__device__ __forceinline__ void gemm_body(
    const __nv_bfloat16* __restrict__ A, const __nv_bfloat16* __restrict__ Wt,
    const float* __restrict__ bias, int mode, float* __restrict__ C,
    __nv_bfloat16* __restrict__ bho, __nv_bfloat16* __restrict__ blo)
{
    extern __shared__ __nv_bfloat16 sm[];
    const int tid = threadIdx.x;
    const int lane = tid & 31, w = tid >> 5;
    const int wm = (w >> 2) << 6;
    const int wn = (w & 3) << 5;
    const int m0 = blockIdx.y << 7, n0 = blockIdx.x << 7;

    const __nv_bfloat16* Ag = A  + (size_t)m0 * K2_;
    const __nv_bfloat16* Wg = Wt + (size_t)n0 * K2_;

    float acc[4][4][4];
#pragma unroll
    for (int mi = 0; mi < 4; mi++)
#pragma unroll
        for (int ni = 0; ni < 4; ni++)
#pragma unroll
            for (int j = 0; j < 4; j++) acc[mi][ni][j] = 0.f;

    const int r0 = tid >> 2,        cI0 = tid & 3;
    const int r1 = (tid >> 2) + 64, cI1 = tid & 3;
    const uint32_t so0 = SWX(r0, cI0), so1 = SWX(r1, cI1);
    const int e0 = cI0 << 3, e1 = cI1 << 3;
#define LOAD_CHUNK2(stage, chunk) do {                                           \
    uint32_t sb = smem_u32((const char*)sm + (stage) * STAGE_B);                 \
    const size_t off = (size_t)(chunk) * 32;                                     \
    CPA16(sb + so0,            Ag + (size_t)r0*K2_ + off + e0);                  \
    CPA16(sb + so1,            Ag + (size_t)r1*K2_ + off + e1);                  \
    CPA16(sb + BUF_B + so0,    Ag + (size_t)r0*K2_ + 2048 + off + e0);           \
    CPA16(sb + BUF_B + so1,    Ag + (size_t)r1*K2_ + 2048 + off + e1);           \
    CPA16(sb + 2*BUF_B + so0,  Wg + (size_t)r0*K2_ + off + e0);                  \
    CPA16(sb + 2*BUF_B + so1,  Wg + (size_t)r1*K2_ + off + e1);                  \
    CPA16(sb + 3*BUF_B + so0,  Wg + (size_t)r0*K2_ + 2048 + off + e0);           \
    CPA16(sb + 3*BUF_B + so1,  Wg + (size_t)r1*K2_ + 2048 + off + e1);           \
    asm volatile("cp.async.commit_group;" ::: "memory");                         \
} while (0)

    LOAD_CHUNK2(0, 0);
    LOAD_CHUNK2(1, 1);

    for (int c = 0; c < NCH2; c++) {
        const int s = c % NSTG;
        if (c + 1 < NCH2) {
            asm volatile("cp.async.wait_group 1;" ::: "memory");
        } else {
            asm volatile("cp.async.wait_group 0;" ::: "memory");
        }
        __syncthreads();

        if (c + 2 < NCH2) LOAD_CHUNK2((c + 2) % NSTG, c + 2);

        const uint32_t sb = smem_u32((const char*)sm + s * STAGE_B);
#pragma unroll
        for (int ks = 0; ks < 2; ks++) {
            const int kbase = ks << 1;
            uint32_t ah[4][4], al[4][4];
#pragma unroll
            for (int mi = 0; mi < 4; mi++) {
                int r = wm + (mi << 4) + (lane & 15);
                int cI = kbase + (lane >> 4);
                uint32_t off = SWX(r, cI);
                LDSM4(ah[mi][0], ah[mi][1], ah[mi][2], ah[mi][3], sb + off);
                LDSM4(al[mi][0], al[mi][1], al[mi][2], al[mi][3], sb + BUF_B + off);
            }
            uint32_t bh[4][2], bl[4][2];
#pragma unroll
            for (int nb = 0; nb < 2; nb++) {
                int r = wn + (nb << 4) + (lane & 7) + (((lane >> 4) & 1) << 3);
                int cI = kbase + ((lane >> 3) & 1);
                uint32_t off = SWX(r, cI);
                LDSM4(bh[nb*2][0], bh[nb*2][1], bh[nb*2+1][0], bh[nb*2+1][1],
                      sb + 2*BUF_B + off);
                LDSM4(bl[nb*2][0], bl[nb*2][1], bl[nb*2+1][0], bl[nb*2+1][1],
                      sb + 3*BUF_B + off);
            }
#pragma unroll
            for (int mi = 0; mi < 4; mi++)
#pragma unroll
                for (int ni = 0; ni < 4; ni++) {
                    MMA16816(acc[mi][ni], ah[mi], bh[ni][0], bh[ni][1]);
                    MMA16816(acc[mi][ni], ah[mi], bl[ni][0], bl[ni][1]);
                    MMA16816(acc[mi][ni], al[mi], bh[ni][0], bh[ni][1]);
                }
        }
    }

    if (mode == 0) {
#pragma unroll
        for (int mi = 0; mi < 4; mi++) {
#pragma unroll
            for (int half = 0; half < 2; half++) {
                int m = m0 + wm + (mi << 4) + (lane >> 2) + (half << 3);
#pragma unroll
                for (int ni = 0; ni < 4; ni++) {
                    int n = n0 + wn + (ni << 3) + ((lane & 3) << 1);
                    float2 o;
                    o.x = acc[mi][ni][half*2+0] + bias[n];
                    o.y = acc[mi][ni][half*2+1] + bias[n+1];
                    *(float2*)(C + (size_t)m * D_ + n) = o;
                }
            }
        }
        return;
    }

    // ---- staged epilogue: fp32 tile in smem, then rope-split or transpose-split
    __syncthreads();                 // mainloop smem reads complete
    float* sf = (float*)sm;
#pragma unroll
    for (int mi = 0; mi < 4; mi++)
#pragma unroll
        for (int half = 0; half < 2; half++) {
            int ml = wm + (mi << 4) + (lane >> 2) + (half << 3);
#pragma unroll
            for (int ni = 0; ni < 4; ni++) {
                int nl = wn + (ni << 3) + ((lane & 3) << 1);
                sf[ml*LDE + nl]     = acc[mi][ni][half*2+0] + bias[n0 + nl];
                sf[ml*LDE + nl + 1] = acc[mi][ni][half*2+1] + bias[n0 + nl + 1];
            }
        }
    __syncthreads();

    const int b  = m0 >> 11;
    const int s0 = m0 & (S_ - 1);
    const int h  = n0 >> 7;
    const int bh = b * H_ + h;

    if (mode == 1) {
        // rope + hi/lo split -> [bh][s][128]
        for (int idx = tid; idx < 128 * 64; idx += 256) {
            int r = idx >> 6, i = idx & 63;
            int s = s0 + r;
            float x1 = sf[r*LDE + i], x2 = sf[r*LDE + 64 + i];
            float cc = g_cos[(s << 6) + i], sn = g_sin[(s << 6) + i];
            float v1 = x1 * cc - x2 * sn;
            float v2 = x2 * cc + x1 * sn;
            size_t o = (((size_t)bh * S_ + s) << 7) + i;
            __nv_bfloat16 h1 = __float2bfloat16(v1);
            __nv_bfloat16 h2 = __float2bfloat16(v2);
            bho[o]      = h1;
            bho[o + 64] = h2;
            blo[o]      = __float2bfloat16(v1 - __bfloat162float(h1));
            blo[o + 64] = __float2bfloat16(v2 - __bfloat162float(h2));
        }
    } else {
        // transpose + hi/lo split -> [bh][d][s]
        for (int idx = tid; idx < 128 * 128; idx += 256) {
            int d = idx >> 7, sl = idx & 127;
            float v = sf[sl*LDE + d];
            __nv_bfloat16 hv = __float2bfloat16(v);
            size_t o = ((size_t)bh * DK_ + d) * S_ + s0 + sl;
            bho[o] = hv;
            blo[o] = __float2bfloat16(v - __bfloat162float(hv));
        }
    }
}

__global__ __launch_bounds__(256, 2) void gemm_qkv(
    const __nv_bfloat16* a0, const __nv_bfloat16* a1, const __nv_bfloat16* a2,
    const __nv_bfloat16* w0, const __nv_bfloat16* w1, const __nv_bfloat16* w2,
    const float* b0, const float* b1, const float* b2,
    __nv_bfloat16* qh, __nv_bfloat16* ql,
    __nv_bfloat16* kh, __nv_bfloat16* kl,
    __nv_bfloat16* vth, __nv_bfloat16* vtl)
{
    int z = blockIdx.z;
    const __nv_bfloat16* A = z == 0 ? a0 : (z == 1 ? a1 : a2);
    const __nv_bfloat16* W = z == 0 ? w0 : (z == 1 ? w1 : w2);
    const float* bias = z == 0 ? b0 : (z == 1 ? b1 : b2);
    __nv_bfloat16* bhp = z == 0 ? qh : (z == 1 ? kh : vth);
    __nv_bfloat16* blp = z == 0 ? ql : (z == 1 ? kl : vtl);
    gemm_body(A, W, bias, z == 2 ? 2 : 1, (float*)0, bhp, blp);
}

__global__ __launch_bounds__(256, 2) void gemm_out(
    const __nv_bfloat16* A, const __nv_bfloat16* W, const float* bias, float* C)
{
    gemm_body(A, W, bias, 0, C, (__nv_bfloat16*)0, (__nv_bfloat16*)0);
}

// ---------------- tensor-core causal flash attention (bf16x3) ----------------
#define QLD 136
#define VLD 72
#define oQH 0
#define oQL 17408
#define oKV 34816
#define stKV 35840
#define ATTN2_SMEM ((oKV + 2*stKV)*2)   // 212992 B

__global__ __launch_bounds__(256, 1) void attn_mma(
    const __nv_bfloat16* __restrict__ gqh, const __nv_bfloat16* __restrict__ gql,
    const __nv_bfloat16* __restrict__ gkh, const __nv_bfloat16* __restrict__ gkl,
    const __nv_bfloat16* __restrict__ gvh, const __nv_bfloat16* __restrict__ gvl,
    __nv_bfloat16* __restrict__ acat)
{
    extern __shared__ __nv_bfloat16 smb[];
    const uint32_t usm = smem_u32(smb);
    const int tid = threadIdx.x;
    const int lane = tid & 31, w = tid >> 5;
    const int wrow = w << 4;
    const int qt = gridDim.x - 1 - blockIdx.x;
    const int bh = blockIdx.y;
    const int b  = bh >> 4, h = bh & 15;
    const int nblk = 2 * qt + 2;
    const float SCL2 = 0.12751743f;

    const size_t qbase = ((size_t)bh * S_ + (size_t)qt * 128) << 7;

    {
#pragma unroll
        for (int i = 0; i < 8; i++) {
            int ch = tid + (i << 8);
            int r = ch >> 4, c8 = (ch & 15) << 3;
            CPA16(usm + (uint32_t)(oQH + r * QLD + c8) * 2, gqh + qbase + ((size_t)r << 7) + c8);
            CPA16(usm + (uint32_t)(oQL + r * QLD + c8) * 2, gql + qbase + ((size_t)r << 7) + c8);
        }
    }
#define LOAD_KV(stage, jb) do {                                                      \
    uint32_t kvb = oKV + (stage) * stKV;                                             \
    size_t kbase = ((size_t)bh * S_ + (size_t)(jb) * 64) << 7;                       \
    _Pragma("unroll")                                                                \
    for (int i = 0; i < 4; i++) {                                                    \
        int ch = tid + (i << 8);                                                     \
        int r = ch >> 4, c8 = (ch & 15) << 3;                                        \
        CPA16(usm + (kvb + r * QLD + c8) * 2,        gkh + kbase + ((size_t)r << 7) + c8); \
        CPA16(usm + (kvb + 8704 + r * QLD + c8) * 2, gkl + kbase + ((size_t)r << 7) + c8); \
    }                                                                                \
    size_t vbase = ((size_t)bh * DK_) * S_ + (size_t)(jb) * 64;                      \
    _Pragma("unroll")                                                                \
    for (int i = 0; i < 4; i++) {                                                    \
        int ch = tid + (i << 8);                                                     \
        int r = ch >> 3, c8 = (ch & 7) << 3;                                         \
        CPA16(usm + (kvb + 17408 + r * VLD + c8) * 2, gvh + vbase + (size_t)r * S_ + c8); \
        CPA16(usm + (kvb + 26624 + r * VLD + c8) * 2, gvl + vbase + (size_t)r * S_ + c8); \
    }                                                                                \
    asm volatile("cp.async.commit_group;" ::: "memory");                             \
} while (0)

    LOAD_KV(0, 0);
    LOAD_KV(1, 1);

    float oa[16][4];
#pragma unroll
    for (int nt = 0; nt < 16; nt++)
#pragma unroll
        for (int j = 0; j < 4; j++) oa[nt][j] = 0.f;
    float m0r = -1e30f, m1r = -1e30f, l0r = 0.f, l1r = 0.f;

    const int grow0 = qt * 128 + wrow + (lane >> 2);
    const int grow1 = grow0 + 8;

    for (int jb = 0; jb < nblk; jb++) {
        const int st = jb & 1;
        if (jb + 1 < nblk) {
            asm volatile("cp.async.wait_group 1;" ::: "memory");
        } else {
            asm volatile("cp.async.wait_group 0;" ::: "memory");
        }
        __syncthreads();

        const uint32_t kvb = oKV + st * stKV;

        float sa[8][4];
#pragma unroll
        for (int nt = 0; nt < 8; nt++)
#pragma unroll
            for (int j = 0; j < 4; j++) sa[nt][j] = 0.f;

#pragma unroll
        for (int kt = 0; kt < 8; kt++) {
            const int kc = kt << 4;
            uint32_t ah[4], al[4];
            {
                int r = wrow + (lane & 15);
                int cc = kc + ((lane >> 4) << 3);
                LDSM4(ah[0], ah[1], ah[2], ah[3], usm + (uint32_t)(oQH + r * QLD + cc) * 2);
                LDSM4(al[0], al[1], al[2], al[3], usm + (uint32_t)(oQL + r * QLD + cc) * 2);
            }
#pragma unroll
            for (int ntp = 0; ntp < 4; ntp++) {
                int r = (ntp << 4) + (lane & 7) + (((lane >> 4) & 1) << 3);
                int cc = kc + (((lane >> 3) & 1) << 3);
                uint32_t bhh[4], bll[4];
                LDSM4(bhh[0], bhh[1], bhh[2], bhh[3], usm + (kvb + r * QLD + cc) * 2);
                LDSM4(bll[0], bll[1], bll[2], bll[3], usm + (kvb + 8704 + r * QLD + cc) * 2);
#pragma unroll
                for (int t = 0; t < 2; t++) {
                    int nt = (ntp << 1) + t;
                    MMA16816(sa[nt], ah, bhh[2*t], bhh[2*t+1]);
                    MMA16816(sa[nt], ah, bll[2*t], bll[2*t+1]);
                    MMA16816(sa[nt], al, bhh[2*t], bhh[2*t+1]);
                }
            }
        }

        const bool needmask = (jb >= 2 * qt);
#pragma unroll
        for (int nt = 0; nt < 8; nt++) {
            int cb = jb * 64 + (nt << 3) + ((lane & 3) << 1);
#pragma unroll
            for (int j = 0; j < 4; j++) {
                float x = sa[nt][j] * SCL2;
                if (needmask) {
                    int col = cb + (j & 1);
                    int row = (j < 2) ? grow0 : grow1;
                    if (col > row) x = -1e30f;
                }
                sa[nt][j] = x;
            }
        }

        float rm0 = -1e30f, rm1 = -1e30f;
#pragma unroll
        for (int nt = 0; nt < 8; nt++) {
            rm0 = fmaxf(rm0, fmaxf(sa[nt][0], sa[nt][1]));
            rm1 = fmaxf(rm1, fmaxf(sa[nt][2], sa[nt][3]));
        }
        rm0 = fmaxf(rm0, __shfl_xor_sync(0xffffffffu, rm0, 1));
        rm0 = fmaxf(rm0, __shfl_xor_sync(0xffffffffu, rm0, 2));
        rm1 = fmaxf(rm1, __shfl_xor_sync(0xffffffffu, rm1, 1));
        rm1 = fmaxf(rm1, __shfl_xor_sync(0xffffffffu, rm1, 2));
        float mn0 = fmaxf(m0r, rm0), mn1 = fmaxf(m1r, rm1);
        float al0 = exp2f(m0r - mn0), al1 = exp2f(m1r - mn1);
        m0r = mn0; m1r = mn1;

        float rs0 = 0.f, rs1 = 0.f;
#pragma unroll
        for (int nt = 0; nt < 8; nt++) {
            float p0 = exp2f(sa[nt][0] - mn0);
            float p1 = exp2f(sa[nt][1] - mn0);
            float p2 = exp2f(sa[nt][2] - mn1);
            float p3 = exp2f(sa[nt][3] - mn1);
            sa[nt][0] = p0; sa[nt][1] = p1; sa[nt][2] = p2; sa[nt][3] = p3;
            rs0 += p0 + p1; rs1 += p2 + p3;
        }
        rs0 += __shfl_xor_sync(0xffffffffu, rs0, 1);
        rs0 += __shfl_xor_sync(0xffffffffu, rs0, 2);
        rs1 += __shfl_xor_sync(0xffffffffu, rs1, 1);
        rs1 += __shfl_xor_sync(0xffffffffu, rs1, 2);
        l0r = l0r * al0 + rs0;
        l1r = l1r * al1 + rs1;

#pragma unroll
        for (int nt = 0; nt < 16; nt++) {
            oa[nt][0] *= al0; oa[nt][1] *= al0;
            oa[nt][2] *= al1; oa[nt][3] *= al1;
        }

#pragma unroll
        for (int kt2 = 0; kt2 < 4; kt2++) {
            const int t0 = kt2 << 1, t1 = t0 + 1;
            uint32_t pah[4], pal[4];
            {
                __nv_bfloat162 hh, ll;
                float p0, p1, r0, r1;
                p0 = sa[t0][0]; p1 = sa[t0][1];
                hh = __floats2bfloat162_rn(p0, p1);
                r0 = p0 - __bfloat162float(hh.x); r1 = p1 - __bfloat162float(hh.y);
                ll = __floats2bfloat162_rn(r0, r1);
                pah[0] = *(uint32_t*)&hh; pal[0] = *(uint32_t*)&ll;
                p0 = sa[t0][2]; p1 = sa[t0][3];
                hh = __floats2bfloat162_rn(p0, p1);
                r0 = p0 - __bfloat162float(hh.x); r1 = p1 - __bfloat162float(hh.y);
                ll = __floats2bfloat162_rn(r0, r1);
                pah[1] = *(uint32_t*)&hh; pal[1] = *(uint32_t*)&ll;
                p0 = sa[t1][0]; p1 = sa[t1][1];
                hh = __floats2bfloat162_rn(p0, p1);
                r0 = p0 - __bfloat162float(hh.x); r1 = p1 - __bfloat162float(hh.y);
                ll = __floats2bfloat162_rn(r0, r1);
                pah[2] = *(uint32_t*)&hh; pal[2] = *(uint32_t*)&ll;
                p0 = sa[t1][2]; p1 = sa[t1][3];
                hh = __floats2bfloat162_rn(p0, p1);
                r0 = p0 - __bfloat162float(hh.x); r1 = p1 - __bfloat162float(hh.y);
                ll = __floats2bfloat162_rn(r0, r1);
                pah[3] = *(uint32_t*)&hh; pal[3] = *(uint32_t*)&ll;
            }
            const int cv = (kt2 << 4) + (((lane >> 3) & 1) << 3);
#pragma unroll
            for (int ntp = 0; ntp < 8; ntp++) {
                int r = (ntp << 4) + (lane & 7) + (((lane >> 4) & 1) << 3);
                uint32_t vhh[4], vll[4];
                LDSM4(vhh[0], vhh[1], vhh[2], vhh[3], usm + (kvb + 17408 + r * VLD + cv) * 2);
                LDSM4(vll[0], vll[1], vll[2], vll[3], usm + (kvb + 26624 + r * VLD + cv) * 2);
#pragma unroll
                for (int t = 0; t < 2; t++) {
                    int nt = (ntp << 1) + t;
                    MMA16816(oa[nt], pah, vhh[2*t], vhh[2*t+1]);
                    MMA16816(oa[nt], pah, vll[2*t], vll[2*t+1]);
                    MMA16816(oa[nt], pal, vhh[2*t], vhh[2*t+1]);
                }
            }
        }

        __syncthreads();
        if (jb + 2 < nblk) LOAD_KV(st, jb + 2);
    }

    float inv0 = 1.f / l0r, inv1 = 1.f / l1r;
    int srow0 = qt * 128 + wrow + (lane >> 2);
    int mrow0 = b * S_ + srow0;
    __nv_bfloat16* a0 = acat + (size_t)mrow0 * K2_ + (h << 7);
    __nv_bfloat16* a1 = a0 + (size_t)8 * K2_;
#pragma unroll
    for (int nt = 0; nt < 16; nt++) {
        int cb = (nt << 3) + ((lane & 3) << 1);
        float v00 = oa[nt][0] * inv0, v01 = oa[nt][1] * inv0;
        float v10 = oa[nt][2] * inv1, v11 = oa[nt][3] * inv1;
        __nv_bfloat162 h0 = __floats2bfloat162_rn(v00, v01);
        __nv_bfloat162 l0p = __floats2bfloat162_rn(v00 - __bfloat162float(h0.x),
                                                   v01 - __bfloat162float(h0.y));
        __nv_bfloat162 h1 = __floats2bfloat162_rn(v10, v11);
        __nv_bfloat162 l1p = __floats2bfloat162_rn(v10 - __bfloat162float(h1.x),
                                                   v11 - __bfloat162float(h1.y));
        *(__nv_bfloat162*)(a0 + cb)        = h0;
        *(__nv_bfloat162*)(a0 + 2048 + cb) = l0p;
        *(__nv_bfloat162*)(a1 + cb)        = h1;
        *(__nv_bfloat162*)(a1 + 2048 + cb) = l1p;
    }
}

// ---------------- launch ----------------
extern "C" void kernel_launch(void* const* d_in, const int* in_sizes, int n_in,
                              void* d_out, int out_size)
{
    const float* query = (const float*)d_in[0];
    const float* key   = (const float*)d_in[1];
    const float* value = (const float*)d_in[2];
    const float* wq = (const float*)d_in[4];
    const float* bq = (const float*)d_in[5];
    const float* wk = (const float*)d_in[6];
    const float* bk = (const float*)d_in[7];
    const float* wv = (const float*)d_in[8];
    const float* bv = (const float*)d_in[9];
    const float* wo = (const float*)d_in[10];
    const float* bo = (const float*)d_in[11];
    float* out = (float*)d_out;

    __nv_bfloat16 *ac0, *ac1, *ac2, *wc0, *wc1, *wc2, *wc3;
    __nv_bfloat16 *qh, *ql, *kh, *kl, *vth, *vtl;
    cudaGetSymbolAddress((void**)&ac0, g_acat0);
    cudaGetSymbolAddress((void**)&ac1, g_acat1);
    cudaGetSymbolAddress((void**)&ac2, g_acat2);
    cudaGetSymbolAddress((void**)&wc0, g_wcat0);
    cudaGetSymbolAddress((void**)&wc1, g_wcat1);
    cudaGetSymbolAddress((void**)&wc2, g_wcat2);
    cudaGetSymbolAddress((void**)&wc3, g_wcat3);
    cudaGetSymbolAddress((void**)&qh, g_qh);
    cudaGetSymbolAddress((void**)&ql, g_ql);
    cudaGetSymbolAddress((void**)&kh, g_kh);
    cudaGetSymbolAddress((void**)&kl, g_kl);
    cudaGetSymbolAddress((void**)&vth, g_vth);
    cudaGetSymbolAddress((void**)&vtl, g_vtl);

    cudaFuncSetAttribute(gemm_qkv, cudaFuncAttributeMaxDynamicSharedMemorySize, GEMM_SMEM);
    cudaFuncSetAttribute(gemm_out, cudaFuncAttributeMaxDynamicSharedMemorySize, GEMM_SMEM);
    cudaFuncSetAttribute(attn_mma, cudaFuncAttributeMaxDynamicSharedMemorySize, ATTN2_SMEM);

    rope_table<<<(S_ * 64) / 256, 256>>>();

    // all 7 hi/lo splits in one launch
    split_all<<<40960, 256>>>(query, key, value, wq, wk, wv, wo,
                              ac0, ac1, ac2, wc0, wc1, wc2, wc3);

    // Q,K,V projections with fused rope-split / transpose-split epilogues
    gemm_qkv<<<dim3(D_/128, M_/128, 3), 256, GEMM_SMEM>>>(
        ac0, ac1, ac2, wc0, wc1, wc2, bq, bk, bv, qh, ql, kh, kl, vth, vtl);

    // attention writes hi/lo split O directly into ac0
    attn_mma<<<dim3(S_ / 128, BH_), 256, ATTN2_SMEM>>>(qh, ql, kh, kl, vth, vtl, ac0);

    // output projection
    gemm_out<<<dim3(D_/128, M_/128), 256, GEMM_SMEM>>>(ac0, wc3, bo, out);
}